// round 10
// baseline (speedup 1.0000x reference)
#include <cuda_runtime.h>
#include <cuda_fp16.h>
#include <cstdint>

#define FULLMASK 0xffffffffu

constexpr int Bsz  = 4096;
constexpr int Ln   = 50;
constexpr int Dm   = 64;
constexpr int ROWS = Bsz * Ln;       // 204800
constexpr int NUNIT = ROWS / 32;     // 6400 32-row units
constexpr int WARPS = 12;

// ---------------- scratch ---------------------------------------------------
__device__ uint32_t g_fjt_h[ROWS * 32];   // fp16x2 packed fjt [row][colpair]
__device__ float g_scores[ROWS];

// ---------------- smem float offsets (k_rows) -------------------------------
constexpr int F_WF  = 0;                  // 28672 floats (7168 uint4)
constexpr int F_ERT = 28672;              // embed_r fp16 LUT (80 uint2)
constexpr int F_B1  = 28992;
constexpr int F_B2  = 29056;
constexpr int F_B3  = 29120;
constexpr int F_BA1 = 29184;
constexpr int F_BA2 = 29248;
constexpr int F_W3  = 29312;
constexpr int F_B3S = 29376;
constexpr int SMEM1_FLOATS = 29380;
constexpr int U_GV1 = 0, U_GV2 = 2048, U_GV3 = 3072, U_AT1 = 4096, U_AT2 = 6144;

// ---------------- helpers ---------------------------------------------------
__device__ __forceinline__ void cpf(float* dst, const float* __restrict__ src, int n) {
    for (int i = threadIdx.x; i < n; i += blockDim.x) dst[i] = src[i];
}
__device__ __forceinline__ uint32_t hpack(float x0, float x1) {
    uint32_t r;
    asm("cvt.rn.f16x2.f32 %0, %1, %2;" : "=r"(r) : "f"(x1), "f"(x0));
    return r;
}
__device__ __forceinline__ void hsplit(float x0, float x1, uint32_t& hi, uint32_t& lo) {
    hi = hpack(x0, x1);
    __half2 h = *reinterpret_cast<__half2*>(&hi);
    float2 f = __half22float2(h);
    lo = hpack(x0 - f.x, x1 - f.y);
}
// NOTE: non-volatile asm — all deps explicit, lets the compiler schedule
__device__ __forceinline__ void mma16816(float4& c, const uint32_t a[4],
                                         uint32_t b0, uint32_t b1) {
    asm("mma.sync.aligned.m16n8k16.row.col.f32.f16.f16.f32 "
        "{%0,%1,%2,%3}, {%4,%5,%6,%7}, {%8,%9}, {%0,%1,%2,%3};\n"
        : "+f"(c.x), "+f"(c.y), "+f"(c.z), "+f"(c.w)
        : "r"(a[0]), "r"(a[1]), "r"(a[2]), "r"(a[3]), "r"(b0), "r"(b1));
}
__device__ __forceinline__ void mma2(float4& c, const uint32_t ah[4], uint4 w) {
    mma16816(c, ah, w.x, w.y);
    mma16816(c, ah, w.z, w.w);
}

// weights [K x 64] -> B-fragment order {hi01, hi89, lo01, lo89}
__device__ void stage_w(uint4* dst, const float* __restrict__ W, int KSTEPS) {
    int total = KSTEPS * 256;
    for (int i = threadIdx.x; i < total; i += blockDim.x) {
        int kk = i >> 8, rem = i & 255, nn = rem >> 5, lane = rem & 31;
        int g = lane >> 2, t2 = (lane & 3) * 2;
        int col = nn * 8 + g;
        int k0 = kk * 16 + t2;
        uint4 e;
        hsplit(W[k0 * 64 + col], W[(k0 + 1) * 64 + col], e.x, e.z);
        hsplit(W[(k0 + 8) * 64 + col], W[(k0 + 9) * 64 + col], e.y, e.w);
        dst[i] = e;
    }
}

__device__ __forceinline__ void bias_act(float4 C[8], const float2* __restrict__ b2,
                                         int t, bool relu) {
#pragma unroll
    for (int nn = 0; nn < 8; nn++) {
        float2 b = b2[nn * 4 + t];
        C[nn].x += b.x; C[nn].y += b.y; C[nn].z += b.x; C[nn].w += b.y;
        if (relu) {
            C[nn].x = fmaxf(C[nn].x, 0.f); C[nn].y = fmaxf(C[nn].y, 0.f);
            C[nn].z = fmaxf(C[nn].z, 0.f); C[nn].w = fmaxf(C[nn].w, 0.f);
        }
    }
}

__device__ __forceinline__ void afrag_fromC(const float4& u, const float4& v,
                                            uint32_t ah[4]) {
    ah[0] = hpack(u.x, u.y);
    ah[1] = hpack(u.z, u.w);
    ah[2] = hpack(v.x, v.y);
    ah[3] = hpack(v.z, v.w);
}

__device__ __forceinline__ void gemm2_fromC(const float4 P0[8], const float4 P1[8],
                                            const uint4* __restrict__ WK, int lane,
                                            float4 C0[8], float4 C1[8]) {
#pragma unroll
    for (int kk = 0; kk < 4; kk++) {
        uint32_t ahA[4], ahB[4];
        afrag_fromC(P0[2 * kk], P0[2 * kk + 1], ahA);
        afrag_fromC(P1[2 * kk], P1[2 * kk + 1], ahB);
        const uint4* wk = WK + kk * 256 + lane;
#pragma unroll
        for (int nn = 0; nn < 8; nn++) {
            uint4 w = wk[nn * 32];
            mma2(C0[nn], ahA, w);
            mma2(C1[nn], ahB, w);
        }
    }
}

// ---------------- K1 ---------------------------------------------------------
__global__ __launch_bounds__(32 * WARPS, 1)
void k_rows(const int* __restrict__ nodes_v, const int* __restrict__ neigh_u,
            const int* __restrict__ neigh_r,
            const float* __restrict__ embed_u, const float* __restrict__ embed_i,
            const float* __restrict__ embed_r,
            const float* __restrict__ gw1, const float* __restrict__ gb1,
            const float* __restrict__ gw2, const float* __restrict__ gb2,
            const float* __restrict__ gw3, const float* __restrict__ gb3,
            const float* __restrict__ aw1, const float* __restrict__ ab1,
            const float* __restrict__ aw2, const float* __restrict__ ab2,
            const float* __restrict__ aw3, const float* __restrict__ ab3) {
    extern __shared__ float sm[];
    uint4* WF = reinterpret_cast<uint4*>(sm + F_WF);
    uint2* ERT = reinterpret_cast<uint2*>(sm + F_ERT);
    stage_w(WF + U_GV1, gw1, 8);
    stage_w(WF + U_GV2, gw2, 4);
    stage_w(WF + U_GV3, gw3, 4);
    stage_w(WF + U_AT1, aw1, 8);
    stage_w(WF + U_AT2, aw2, 4);
    for (int i = threadIdx.x; i < 80; i += blockDim.x) {
        int rr = i >> 4, kk = (i >> 2) & 3, t = i & 3;
        int c = kk * 16 + t * 2;
        const float* er = embed_r + rr * 64;
        uint2 e;
        e.x = hpack(er[c], er[c + 1]);
        e.y = hpack(er[c + 8], er[c + 9]);
        ERT[i] = e;
    }
    cpf(sm + F_B1,  gb1, 64);
    cpf(sm + F_B2,  gb2, 64);
    cpf(sm + F_B3,  gb3, 64);
    cpf(sm + F_BA1, ab1, 64);
    cpf(sm + F_BA2, ab2, 64);
    cpf(sm + F_W3,  aw3, 64);
    if (threadIdx.x == 0) sm[F_B3S] = ab3[0];
    __syncthreads();

    const int wid  = threadIdx.x >> 5;
    const int lane = threadIdx.x & 31;
    const int g    = lane >> 2;
    const int t    = lane & 3;
    const int t2   = t * 2;
    const float b3 = sm[F_B3S];

    const int wg      = blockIdx.x * WARPS + wid;
    const int wstride = gridDim.x * WARPS;

    for (int unit = wg; unit < NUNIT; unit += wstride) {
        const int row0 = unit * 32;
        int u0 = neigh_u[row0 + g],      u1 = neigh_u[row0 + 8 + g];
        int u2 = neigh_u[row0 + 16 + g], u3 = neigh_u[row0 + 24 + g];
        int r0i = neigh_r[row0 + g],      r1i = neigh_r[row0 + 8 + g];
        int r2i = neigh_r[row0 + 16 + g], r3i = neigh_r[row0 + 24 + g];
        const float* eu0 = embed_u + (size_t)u0 * 64;
        const float* eu1 = embed_u + (size_t)u1 * 64;
        const float* eu2 = embed_u + (size_t)u2 * 64;
        const float* eu3 = embed_u + (size_t)u3 * 64;

        // ---- batch-load + convert pt activations (all 4 k-steps up front)
        uint32_t FA[16], FB[16];
#pragma unroll
        for (int kk = 0; kk < 4; kk++) {
            int c = kk * 16 + t2;
            float2 a0 = *(const float2*)(eu0 + c);
            float2 a1 = *(const float2*)(eu1 + c);
            float2 a2 = *(const float2*)(eu0 + c + 8);
            float2 a3 = *(const float2*)(eu1 + c + 8);
            float2 b0 = *(const float2*)(eu2 + c);
            float2 b1 = *(const float2*)(eu3 + c);
            float2 b2 = *(const float2*)(eu2 + c + 8);
            float2 b3v = *(const float2*)(eu3 + c + 8);
            FA[kk * 4 + 0] = hpack(a0.x, a0.y);
            FA[kk * 4 + 1] = hpack(a1.x, a1.y);
            FA[kk * 4 + 2] = hpack(a2.x, a2.y);
            FA[kk * 4 + 3] = hpack(a3.x, a3.y);
            FB[kk * 4 + 0] = hpack(b0.x, b0.y);
            FB[kk * 4 + 1] = hpack(b1.x, b1.y);
            FB[kk * 4 + 2] = hpack(b2.x, b2.y);
            FB[kk * 4 + 3] = hpack(b3v.x, b3v.y);
        }

        float4 C0[8] = {}, C1[8] = {};
        // ---- gv1, k-steps 0..3 (pt from regs)
#pragma unroll
        for (int kk = 0; kk < 4; kk++) {
            const uint4* wk = WF + U_GV1 + kk * 256 + lane;
#pragma unroll
            for (int nn = 0; nn < 8; nn++) {
                uint4 w = wk[nn * 32];
                mma2(C0[nn], &FA[kk * 4], w);
                mma2(C1[nn], &FB[kk * 4], w);
            }
        }
        // ---- gv1, k-steps 4..7 (er from LUT)
#pragma unroll
        for (int kk = 0; kk < 4; kk++) {
            uint2 eA0 = ERT[(r0i * 4 + kk) * 4 + t];
            uint2 eA1 = ERT[(r1i * 4 + kk) * 4 + t];
            uint2 eB0 = ERT[(r2i * 4 + kk) * 4 + t];
            uint2 eB1 = ERT[(r3i * 4 + kk) * 4 + t];
            uint32_t ahA[4] = {eA0.x, eA1.x, eA0.y, eA1.y};
            uint32_t ahB[4] = {eB0.x, eB1.x, eB0.y, eB1.y};
            const uint4* wk = WF + U_GV1 + (kk + 4) * 256 + lane;
#pragma unroll
            for (int nn = 0; nn < 8; nn++) {
                uint4 w = wk[nn * 32];
                mma2(C0[nn], ahA, w);
                mma2(C1[nn], ahB, w);
            }
        }
        bias_act(C0, (const float2*)(sm + F_B1), t, true);
        bias_act(C1, (const float2*)(sm + F_B1), t, true);

        float4 D0[8] = {}, D1[8] = {};
        gemm2_fromC(C0, C1, WF + U_GV2, lane, D0, D1);
        bias_act(D0, (const float2*)(sm + F_B2), t, true);
        bias_act(D1, (const float2*)(sm + F_B2), t, true);

#pragma unroll
        for (int nn = 0; nn < 8; nn++) {
            C0[nn] = make_float4(0.f, 0.f, 0.f, 0.f);
            C1[nn] = make_float4(0.f, 0.f, 0.f, 0.f);
        }
        gemm2_fromC(D0, D1, WF + U_GV3, lane, C0, C1);
        bias_act(C0, (const float2*)(sm + F_B3), t, false);
        bias_act(C1, (const float2*)(sm + F_B3), t, false);   // C = fjt frags

        // ---- fjt -> global as fp16x2 (half traffic)
#pragma unroll
        for (int nn = 0; nn < 8; nn++) {
            int c4 = nn * 4 + t;
            g_fjt_h[(row0 + g) * 32 + c4]      = hpack(C0[nn].x, C0[nn].y);
            g_fjt_h[(row0 + 8 + g) * 32 + c4]  = hpack(C0[nn].z, C0[nn].w);
            g_fjt_h[(row0 + 16 + g) * 32 + c4] = hpack(C1[nn].x, C1[nn].y);
            g_fjt_h[(row0 + 24 + g) * 32 + c4] = hpack(C1[nn].z, C1[nn].w);
        }

        // ---- qj pointers and batch-load + convert (before fromC work)
        int b0i = row0 / Ln;
        int rof = row0 - b0i * Ln;
        int nv0 = nodes_v[b0i];
        int nv1 = nodes_v[(b0i + 1 < Bsz) ? b0i + 1 : Bsz - 1];
        const float* ei0 = embed_i + (size_t)((rof + g      >= Ln) ? nv1 : nv0) * 64;
        const float* ei1 = embed_i + (size_t)((rof + 8 + g  >= Ln) ? nv1 : nv0) * 64;
        const float* ei2 = embed_i + (size_t)((rof + 16 + g >= Ln) ? nv1 : nv0) * 64;
        const float* ei3 = embed_i + (size_t)((rof + 24 + g >= Ln) ? nv1 : nv0) * 64;
        uint32_t QA[16], QB[16];
#pragma unroll
        for (int kk = 0; kk < 4; kk++) {
            int c = kk * 16 + t2;
            float2 xa0 = *(const float2*)(ei0 + c);
            float2 xa1 = *(const float2*)(ei1 + c);
            float2 xa2 = *(const float2*)(ei0 + c + 8);
            float2 xa3 = *(const float2*)(ei1 + c + 8);
            float2 xb0 = *(const float2*)(ei2 + c);
            float2 xb1 = *(const float2*)(ei3 + c);
            float2 xb2 = *(const float2*)(ei2 + c + 8);
            float2 xb3 = *(const float2*)(ei3 + c + 8);
            QA[kk * 4 + 0] = hpack(xa0.x, xa0.y);
            QA[kk * 4 + 1] = hpack(xa1.x, xa1.y);
            QA[kk * 4 + 2] = hpack(xa2.x, xa2.y);
            QA[kk * 4 + 3] = hpack(xa3.x, xa3.y);
            QB[kk * 4 + 0] = hpack(xb0.x, xb0.y);
            QB[kk * 4 + 1] = hpack(xb1.x, xb1.y);
            QB[kk * 4 + 2] = hpack(xb2.x, xb2.y);
            QB[kk * 4 + 3] = hpack(xb3.x, xb3.y);
        }

        // ---- at1: k 0..3 from fjt frags, k 4..7 from qj regs
#pragma unroll
        for (int nn = 0; nn < 8; nn++) {
            D0[nn] = make_float4(0.f, 0.f, 0.f, 0.f);
            D1[nn] = make_float4(0.f, 0.f, 0.f, 0.f);
        }
#pragma unroll
        for (int kk = 0; kk < 4; kk++) {
            uint32_t ahA[4], ahB[4];
            afrag_fromC(C0[2 * kk], C0[2 * kk + 1], ahA);
            afrag_fromC(C1[2 * kk], C1[2 * kk + 1], ahB);
            const uint4* wk = WF + U_AT1 + kk * 256 + lane;
#pragma unroll
            for (int nn = 0; nn < 8; nn++) {
                uint4 w = wk[nn * 32];
                mma2(D0[nn], ahA, w);
                mma2(D1[nn], ahB, w);
            }
        }
#pragma unroll
        for (int kk = 0; kk < 4; kk++) {
            const uint4* wk = WF + U_AT1 + (kk + 4) * 256 + lane;
#pragma unroll
            for (int nn = 0; nn < 8; nn++) {
                uint4 w = wk[nn * 32];
                mma2(D0[nn], &QA[kk * 4], w);
                mma2(D1[nn], &QB[kk * 4], w);
            }
        }
        bias_act(D0, (const float2*)(sm + F_BA1), t, true);
        bias_act(D1, (const float2*)(sm + F_BA1), t, true);

#pragma unroll
        for (int nn = 0; nn < 8; nn++) {
            C0[nn] = make_float4(0.f, 0.f, 0.f, 0.f);
            C1[nn] = make_float4(0.f, 0.f, 0.f, 0.f);
        }
        gemm2_fromC(D0, D1, WF + U_AT2, lane, C0, C1);
        bias_act(C0, (const float2*)(sm + F_BA2), t, true);
        bias_act(C1, (const float2*)(sm + F_BA2), t, true);

        // ---- scores
        const float2* w32 = (const float2*)(sm + F_W3);
        float sA0 = 0.f, sA1 = 0.f, sB0 = 0.f, sB1 = 0.f;
#pragma unroll
        for (int nn = 0; nn < 8; nn++) {
            float2 w = w32[nn * 4 + t];
            sA0 += C0[nn].x * w.x + C0[nn].y * w.y;
            sA1 += C0[nn].z * w.x + C0[nn].w * w.y;
            sB0 += C1[nn].x * w.x + C1[nn].y * w.y;
            sB1 += C1[nn].z * w.x + C1[nn].w * w.y;
        }
        sA0 += __shfl_xor_sync(FULLMASK, sA0, 1); sA0 += __shfl_xor_sync(FULLMASK, sA0, 2);
        sA1 += __shfl_xor_sync(FULLMASK, sA1, 1); sA1 += __shfl_xor_sync(FULLMASK, sA1, 2);
        sB0 += __shfl_xor_sync(FULLMASK, sB0, 1); sB0 += __shfl_xor_sync(FULLMASK, sB0, 2);
        sB1 += __shfl_xor_sync(FULLMASK, sB1, 1); sB1 += __shfl_xor_sync(FULLMASK, sB1, 2);
        if (t == 0) {
            g_scores[row0 + g]      = sA0 + b3;
            g_scores[row0 + 8 + g]  = sA1 + b3;
            g_scores[row0 + 16 + g] = sB0 + b3;
            g_scores[row0 + 24 + g] = sB1 + b3;
        }
    }
}

// ---------------- K2: softmax + aggregation + combine MLP -------------------
__device__ __forceinline__ float wredmax(float v) {
#pragma unroll
    for (int o = 16; o; o >>= 1) v = fmaxf(v, __shfl_xor_sync(FULLMASK, v, o));
    return v;
}
__device__ __forceinline__ float wredsum(float v) {
#pragma unroll
    for (int o = 16; o; o >>= 1) v += __shfl_xor_sync(FULLMASK, v, o);
    return v;
}
constexpr int AGG_WARPS = 16;
constexpr int OFF_W1  = 0;
constexpr int OFF_W2  = 8192;
constexpr int OFF_B1  = 12288;
constexpr int OFF_B2  = 12352;
constexpr int OFF_XB2 = 12416;
constexpr int OFF_MU  = OFF_XB2 + AGG_WARPS * 128;
constexpr int SMEM2_FLOATS = OFF_MU + AGG_WARPS * 64;

template <int K, bool RELU>
__device__ __forceinline__ void mlp1(const float* __restrict__ W,
                                     const float* __restrict__ bias,
                                     const float* __restrict__ xb, int lane,
                                     float& o0, float& o1) {
    float c0 = 0.f, c1 = 0.f;
#pragma unroll 8
    for (int k = 0; k < K; k++) {
        float x = xb[k];
        c0 = fmaf(x, W[k * Dm + lane], c0);
        c1 = fmaf(x, W[k * Dm + lane + 32], c1);
    }
    c0 += bias[lane]; c1 += bias[lane + 32];
    if (RELU) { c0 = fmaxf(c0, 0.f); c1 = fmaxf(c1, 0.f); }
    o0 = c0; o1 = c1;
}

__global__ __launch_bounds__(32 * AGG_WARPS, 2)
void k_agg(const int* __restrict__ nodes_v, const float* __restrict__ embed_i,
           const float* __restrict__ w1, const float* __restrict__ b1,
           const float* __restrict__ w2, const float* __restrict__ b2,
           float* __restrict__ out) {
    extern __shared__ float smf[];
    cpf(smf + OFF_W1, w1, 8192);
    cpf(smf + OFF_W2, w2, 4096);
    cpf(smf + OFF_B1, b1, 64);
    cpf(smf + OFF_B2, b2, 64);
    __syncthreads();

    const int wid  = threadIdx.x >> 5;
    const int lane = threadIdx.x & 31;
    float* xb = smf + OFF_XB2 + wid * 128;
    float* mu = smf + OFF_MU  + wid * 64;

    for (int b = blockIdx.x * AGG_WARPS + wid; b < Bsz; b += gridDim.x * AGG_WARPS) {
        const float* sc = g_scores + b * Ln;
        float s0 = (lane < Ln)        ? sc[lane]      : -1e30f;
        float s1 = ((lane + 32) < Ln) ? sc[lane + 32] : -1e30f;
        float m  = wredmax(fmaxf(s0, s1));
        float e0 = (lane < Ln)        ? expf(s0 - m) : 0.f;
        float e1 = ((lane + 32) < Ln) ? expf(s1 - m) : 0.f;
        float inv = 1.f / wredsum(e0 + e1);
        mu[lane]      = e0 * inv;
        mu[lane + 32] = e1 * inv;
        __syncwarp();

        // zj from fp16-packed fjt: 1 LDG.32 + cvt per l
        float ax = 0.f, ay = 0.f;
        const uint32_t* fj = g_fjt_h + (size_t)b * Ln * 32;
#pragma unroll 10
        for (int l = 0; l < Ln; l++) {
            float mm = mu[l];
            uint32_t v = fj[l * 32 + lane];
            float2 f = __half22float2(*reinterpret_cast<const __half2*>(&v));
            ax = fmaf(mm, f.x, ax);
            ay = fmaf(mm, f.y, ay);
        }
        ((float2*)xb)[lane] = make_float2(ax, ay);
        int iv = nodes_v[b];
        ((float2*)(xb + 64))[lane] = ((const float2*)embed_i)[iv * 32 + lane];
        __syncwarp();

        float z0, z1;
        mlp1<128, true>(smf + OFF_W1, smf + OFF_B1, xb, lane, z0, z1);
        __syncwarp();
        xb[lane]      = z0;
        xb[lane + 32] = z1;
        __syncwarp();
        float o0, o1;
        mlp1<64, true>(smf + OFF_W2, smf + OFF_B2, xb, lane, o0, o1);
        out[b * Dm + lane]      = o0;
        out[b * Dm + lane + 32] = o1;
        __syncwarp();
    }
}

// ---------------- launch ----------------------------------------------------
extern "C" void kernel_launch(void* const* d_in, const int* in_sizes, int n_in,
                              void* d_out, int out_size) {
    const int*   nodes_v = (const int*)d_in[0];
    const int*   neigh_u = (const int*)d_in[1];
    const int*   neigh_r = (const int*)d_in[2];
    const float* embed_u = (const float*)d_in[3];
    const float* embed_i = (const float*)d_in[4];
    const float* embed_r = (const float*)d_in[5];
    const float* gv_w1 = (const float*)d_in[6];
    const float* gv_b1 = (const float*)d_in[7];
    const float* gv_w2 = (const float*)d_in[8];
    const float* gv_b2 = (const float*)d_in[9];
    const float* gv_w3 = (const float*)d_in[10];
    const float* gv_b3 = (const float*)d_in[11];
    const float* at_w1 = (const float*)d_in[12];
    const float* at_b1 = (const float*)d_in[13];
    const float* at_w2 = (const float*)d_in[14];
    const float* at_b2 = (const float*)d_in[15];
    const float* at_w3 = (const float*)d_in[16];
    const float* at_b3 = (const float*)d_in[17];
    const float* wr1_w = (const float*)d_in[18];
    const float* wr1_b = (const float*)d_in[19];
    const float* wr2_w = (const float*)d_in[20];
    const float* wr2_b = (const float*)d_in[21];
    float* out = (float*)d_out;

    int nsm = 148;
    cudaDeviceGetAttribute(&nsm, cudaDevAttrMultiProcessorCount, 0);

    const size_t s1 = SMEM1_FLOATS * sizeof(float);
    const size_t s2 = SMEM2_FLOATS * sizeof(float);
    cudaFuncSetAttribute(k_rows, cudaFuncAttributeMaxDynamicSharedMemorySize, (int)s1);
    cudaFuncSetAttribute(k_agg,  cudaFuncAttributeMaxDynamicSharedMemorySize, (int)s2);

    k_rows<<<nsm, 32 * WARPS, s1>>>(nodes_v, neigh_u, neigh_r,
                                    embed_u, embed_i, embed_r,
                                    gv_w1, gv_b1, gv_w2, gv_b2, gv_w3, gv_b3,
                                    at_w1, at_b1, at_w2, at_b2, at_w3, at_b3);
    k_agg<<<2 * nsm, 32 * AGG_WARPS, s2>>>(nodes_v, embed_i,
                                           wr1_w, wr1_b, wr2_w, wr2_b, out);
}

// round 11
// speedup vs baseline: 1.8156x; 1.8156x over previous
#include <cuda_runtime.h>
#include <cuda_fp16.h>
#include <cstdint>

#define FULLMASK 0xffffffffu

constexpr int Bsz  = 4096;
constexpr int Ln   = 50;
constexpr int Dm   = 64;
constexpr int ROWS = Bsz * Ln;       // 204800
constexpr int NUNIT = ROWS / 32;     // 6400 32-row units
constexpr int WARPS = 12;

// ---------------- scratch ---------------------------------------------------
__device__ uint32_t g_fjt_h[ROWS * 32];   // fp16x2 packed fjt [row][colpair]
__device__ float g_scores[ROWS];

// ---------------- smem float offsets (k_rows) -------------------------------
constexpr int F_WF  = 0;                  // 28672 floats (7168 uint4)
constexpr int F_ERT = 28672;              // embed_r fp16 LUT (80 uint2)
constexpr int F_B1  = 28992;
constexpr int F_B2  = 29056;
constexpr int F_B3  = 29120;
constexpr int F_BA1 = 29184;
constexpr int F_BA2 = 29248;
constexpr int F_W3  = 29312;
constexpr int F_B3S = 29376;
constexpr int SMEM1_FLOATS = 29380;
constexpr int U_GV1 = 0, U_GV2 = 2048, U_GV3 = 3072, U_AT1 = 4096, U_AT2 = 6144;

// ---------------- helpers ---------------------------------------------------
__device__ __forceinline__ void cpf(float* dst, const float* __restrict__ src, int n) {
    for (int i = threadIdx.x; i < n; i += blockDim.x) dst[i] = src[i];
}
__device__ __forceinline__ uint32_t hpack(float x0, float x1) {
    uint32_t r;
    asm("cvt.rn.f16x2.f32 %0, %1, %2;" : "=r"(r) : "f"(x1), "f"(x0));
    return r;
}
__device__ __forceinline__ void hsplit(float x0, float x1, uint32_t& hi, uint32_t& lo) {
    hi = hpack(x0, x1);
    __half2 h = *reinterpret_cast<__half2*>(&hi);
    float2 f = __half22float2(h);
    lo = hpack(x0 - f.x, x1 - f.y);
}
__device__ __forceinline__ void mma16816(float4& c, const uint32_t a[4],
                                         uint32_t b0, uint32_t b1) {
    asm volatile(
        "mma.sync.aligned.m16n8k16.row.col.f32.f16.f16.f32 "
        "{%0,%1,%2,%3}, {%4,%5,%6,%7}, {%8,%9}, {%0,%1,%2,%3};\n"
        : "+f"(c.x), "+f"(c.y), "+f"(c.z), "+f"(c.w)
        : "r"(a[0]), "r"(a[1]), "r"(a[2]), "r"(a[3]), "r"(b0), "r"(b1));
}
// 2-term: C += A*Whi + A*Wlo  (w = {hi01, hi89, lo01, lo89})
__device__ __forceinline__ void mma2(float4& c, const uint32_t ah[4], uint4 w) {
    mma16816(c, ah, w.x, w.y);
    mma16816(c, ah, w.z, w.w);
}

// weights [K x 64] -> B-fragment order {hi01, hi89, lo01, lo89} (fp16 split)
__device__ void stage_w(uint4* dst, const float* __restrict__ W, int KSTEPS) {
    int total = KSTEPS * 256;
    for (int i = threadIdx.x; i < total; i += blockDim.x) {
        int kk = i >> 8, rem = i & 255, nn = rem >> 5, lane = rem & 31;
        int g = lane >> 2, t2 = (lane & 3) * 2;
        int col = nn * 8 + g;
        int k0 = kk * 16 + t2;
        uint4 e;
        hsplit(W[k0 * 64 + col], W[(k0 + 1) * 64 + col], e.x, e.z);
        hsplit(W[(k0 + 8) * 64 + col], W[(k0 + 9) * 64 + col], e.y, e.w);
        dst[i] = e;
    }
}

__device__ __forceinline__ void bias_act(float4 C[8], const float2* __restrict__ b2,
                                         int t, bool relu) {
#pragma unroll
    for (int nn = 0; nn < 8; nn++) {
        float2 b = b2[nn * 4 + t];
        C[nn].x += b.x; C[nn].y += b.y; C[nn].z += b.x; C[nn].w += b.y;
        if (relu) {
            C[nn].x = fmaxf(C[nn].x, 0.f); C[nn].y = fmaxf(C[nn].y, 0.f);
            C[nn].z = fmaxf(C[nn].z, 0.f); C[nn].w = fmaxf(C[nn].w, 0.f);
        }
    }
}

__device__ __forceinline__ void afrag_fromC(const float4& u, const float4& v,
                                            uint32_t ah[4]) {
    ah[0] = hpack(u.x, u.y);
    ah[1] = hpack(u.z, u.w);
    ah[2] = hpack(v.x, v.y);
    ah[3] = hpack(v.z, v.w);
}

// dual-half fromC GEMM (K=64): halves share each weight fragment read
__device__ __forceinline__ void gemm2_fromC(const float4 P0[8], const float4 P1[8],
                                            const uint4* __restrict__ WK, int lane,
                                            float4 C0[8], float4 C1[8]) {
#pragma unroll
    for (int kk = 0; kk < 4; kk++) {
        uint32_t ahA[4], ahB[4];
        afrag_fromC(P0[2 * kk], P0[2 * kk + 1], ahA);
        afrag_fromC(P1[2 * kk], P1[2 * kk + 1], ahB);
        const uint4* wk = WK + kk * 256 + lane;
#pragma unroll
        for (int nn = 0; nn < 8; nn++) {
            uint4 w = wk[nn * 32];
            mma2(C0[nn], ahA, w);
            mma2(C1[nn], ahB, w);
        }
    }
}

// ---------------- K1: fused row MLPs, M=32/warp, fp16 2-term ----------------
__global__ __launch_bounds__(32 * WARPS, 1)
void k_rows(const int* __restrict__ nodes_v, const int* __restrict__ neigh_u,
            const int* __restrict__ neigh_r,
            const float* __restrict__ embed_u, const float* __restrict__ embed_i,
            const float* __restrict__ embed_r,
            const float* __restrict__ gw1, const float* __restrict__ gb1,
            const float* __restrict__ gw2, const float* __restrict__ gb2,
            const float* __restrict__ gw3, const float* __restrict__ gb3,
            const float* __restrict__ aw1, const float* __restrict__ ab1,
            const float* __restrict__ aw2, const float* __restrict__ ab2,
            const float* __restrict__ aw3, const float* __restrict__ ab3) {
    extern __shared__ float sm[];
    uint4* WF = reinterpret_cast<uint4*>(sm + F_WF);
    uint2* ERT = reinterpret_cast<uint2*>(sm + F_ERT);
    stage_w(WF + U_GV1, gw1, 8);
    stage_w(WF + U_GV2, gw2, 4);
    stage_w(WF + U_GV3, gw3, 4);
    stage_w(WF + U_AT1, aw1, 8);
    stage_w(WF + U_AT2, aw2, 4);
    // embed_r activation LUT (single fp16): [rr][kk][t] -> {a01, a89}
    for (int i = threadIdx.x; i < 80; i += blockDim.x) {
        int rr = i >> 4, kk = (i >> 2) & 3, t = i & 3;
        int c = kk * 16 + t * 2;
        const float* er = embed_r + rr * 64;
        uint2 e;
        e.x = hpack(er[c], er[c + 1]);
        e.y = hpack(er[c + 8], er[c + 9]);
        ERT[i] = e;
    }
    cpf(sm + F_B1,  gb1, 64);
    cpf(sm + F_B2,  gb2, 64);
    cpf(sm + F_B3,  gb3, 64);
    cpf(sm + F_BA1, ab1, 64);
    cpf(sm + F_BA2, ab2, 64);
    cpf(sm + F_W3,  aw3, 64);
    if (threadIdx.x == 0) sm[F_B3S] = ab3[0];
    __syncthreads();

    const int wid  = threadIdx.x >> 5;
    const int lane = threadIdx.x & 31;
    const int g    = lane >> 2;
    const int t    = lane & 3;
    const int t2   = t * 2;
    const float b3 = sm[F_B3S];

    const int wg      = blockIdx.x * WARPS + wid;
    const int wstride = gridDim.x * WARPS;

    for (int unit = wg; unit < NUNIT; unit += wstride) {
        const int row0 = unit * 32;
        int u0 = neigh_u[row0 + g],      u1 = neigh_u[row0 + 8 + g];
        int u2 = neigh_u[row0 + 16 + g], u3 = neigh_u[row0 + 24 + g];
        int r0i = neigh_r[row0 + g],      r1i = neigh_r[row0 + 8 + g];
        int r2i = neigh_r[row0 + 16 + g], r3i = neigh_r[row0 + 24 + g];
        const float* eu0 = embed_u + (size_t)u0 * 64;
        const float* eu1 = embed_u + (size_t)u1 * 64;
        const float* eu2 = embed_u + (size_t)u2 * 64;
        const float* eu3 = embed_u + (size_t)u3 * 64;

        float4 C0[8] = {}, C1[8] = {};
        // ---- gv1, k-steps 0..3 (pt, JIT global loads -> single fp16)
#pragma unroll
        for (int kk = 0; kk < 4; kk++) {
            int c = kk * 16 + t2;
            float2 a0 = *(const float2*)(eu0 + c);
            float2 a1 = *(const float2*)(eu1 + c);
            float2 a2 = *(const float2*)(eu0 + c + 8);
            float2 a3 = *(const float2*)(eu1 + c + 8);
            float2 b0 = *(const float2*)(eu2 + c);
            float2 b1 = *(const float2*)(eu3 + c);
            float2 b2 = *(const float2*)(eu2 + c + 8);
            float2 b3v = *(const float2*)(eu3 + c + 8);
            uint32_t ahA[4], ahB[4];
            ahA[0] = hpack(a0.x, a0.y); ahA[1] = hpack(a1.x, a1.y);
            ahA[2] = hpack(a2.x, a2.y); ahA[3] = hpack(a3.x, a3.y);
            ahB[0] = hpack(b0.x, b0.y); ahB[1] = hpack(b1.x, b1.y);
            ahB[2] = hpack(b2.x, b2.y); ahB[3] = hpack(b3v.x, b3v.y);
            const uint4* wk = WF + U_GV1 + kk * 256 + lane;
#pragma unroll
            for (int nn = 0; nn < 8; nn++) {
                uint4 w = wk[nn * 32];
                mma2(C0[nn], ahA, w);
                mma2(C1[nn], ahB, w);
            }
        }
        // ---- gv1, k-steps 4..7 (er from LUT)
#pragma unroll
        for (int kk = 0; kk < 4; kk++) {
            uint2 eA0 = ERT[(r0i * 4 + kk) * 4 + t];
            uint2 eA1 = ERT[(r1i * 4 + kk) * 4 + t];
            uint2 eB0 = ERT[(r2i * 4 + kk) * 4 + t];
            uint2 eB1 = ERT[(r3i * 4 + kk) * 4 + t];
            uint32_t ahA[4] = {eA0.x, eA1.x, eA0.y, eA1.y};
            uint32_t ahB[4] = {eB0.x, eB1.x, eB0.y, eB1.y};
            const uint4* wk = WF + U_GV1 + (kk + 4) * 256 + lane;
#pragma unroll
            for (int nn = 0; nn < 8; nn++) {
                uint4 w = wk[nn * 32];
                mma2(C0[nn], ahA, w);
                mma2(C1[nn], ahB, w);
            }
        }
        bias_act(C0, (const float2*)(sm + F_B1), t, true);
        bias_act(C1, (const float2*)(sm + F_B1), t, true);

        float4 D0[8] = {}, D1[8] = {};
        gemm2_fromC(C0, C1, WF + U_GV2, lane, D0, D1);
        bias_act(D0, (const float2*)(sm + F_B2), t, true);
        bias_act(D1, (const float2*)(sm + F_B2), t, true);

#pragma unroll
        for (int nn = 0; nn < 8; nn++) {
            C0[nn] = make_float4(0.f, 0.f, 0.f, 0.f);
            C1[nn] = make_float4(0.f, 0.f, 0.f, 0.f);
        }
        gemm2_fromC(D0, D1, WF + U_GV3, lane, C0, C1);
        bias_act(C0, (const float2*)(sm + F_B3), t, false);
        bias_act(C1, (const float2*)(sm + F_B3), t, false);   // C = fjt frags

        // ---- fjt -> global as fp16x2 (half traffic, low reg cost)
#pragma unroll
        for (int nn = 0; nn < 8; nn++) {
            int c4 = nn * 4 + t;
            g_fjt_h[(row0 + g) * 32 + c4]      = hpack(C0[nn].x, C0[nn].y);
            g_fjt_h[(row0 + 8 + g) * 32 + c4]  = hpack(C0[nn].z, C0[nn].w);
            g_fjt_h[(row0 + 16 + g) * 32 + c4] = hpack(C1[nn].x, C1[nn].y);
            g_fjt_h[(row0 + 24 + g) * 32 + c4] = hpack(C1[nn].z, C1[nn].w);
        }

        // ---- qj row pointers (<=2 distinct b per 32-row unit)
        int b0i = row0 / Ln;
        int rof = row0 - b0i * Ln;
        int nv0 = nodes_v[b0i];
        int nv1 = nodes_v[(b0i + 1 < Bsz) ? b0i + 1 : Bsz - 1];
        const float* ei0 = embed_i + (size_t)((rof + g      >= Ln) ? nv1 : nv0) * 64;
        const float* ei1 = embed_i + (size_t)((rof + 8 + g  >= Ln) ? nv1 : nv0) * 64;
        const float* ei2 = embed_i + (size_t)((rof + 16 + g >= Ln) ? nv1 : nv0) * 64;
        const float* ei3 = embed_i + (size_t)((rof + 24 + g >= Ln) ? nv1 : nv0) * 64;

        // ---- at1: k 0..3 from fjt frags, k 4..7 from qj (JIT loads)
#pragma unroll
        for (int nn = 0; nn < 8; nn++) {
            D0[nn] = make_float4(0.f, 0.f, 0.f, 0.f);
            D1[nn] = make_float4(0.f, 0.f, 0.f, 0.f);
        }
#pragma unroll
        for (int kk = 0; kk < 4; kk++) {
            uint32_t ahA[4], ahB[4];
            afrag_fromC(C0[2 * kk], C0[2 * kk + 1], ahA);
            afrag_fromC(C1[2 * kk], C1[2 * kk + 1], ahB);
            const uint4* wk = WF + U_AT1 + kk * 256 + lane;
#pragma unroll
            for (int nn = 0; nn < 8; nn++) {
                uint4 w = wk[nn * 32];
                mma2(D0[nn], ahA, w);
                mma2(D1[nn], ahB, w);
            }
        }
#pragma unroll
        for (int kk = 0; kk < 4; kk++) {
            int c = kk * 16 + t2;
            float2 xa0 = *(const float2*)(ei0 + c);
            float2 xa1 = *(const float2*)(ei1 + c);
            float2 xa2 = *(const float2*)(ei0 + c + 8);
            float2 xa3 = *(const float2*)(ei1 + c + 8);
            float2 xb0 = *(const float2*)(ei2 + c);
            float2 xb1 = *(const float2*)(ei3 + c);
            float2 xb2 = *(const float2*)(ei2 + c + 8);
            float2 xb3 = *(const float2*)(ei3 + c + 8);
            uint32_t ahA[4], ahB[4];
            ahA[0] = hpack(xa0.x, xa0.y); ahA[1] = hpack(xa1.x, xa1.y);
            ahA[2] = hpack(xa2.x, xa2.y); ahA[3] = hpack(xa3.x, xa3.y);
            ahB[0] = hpack(xb0.x, xb0.y); ahB[1] = hpack(xb1.x, xb1.y);
            ahB[2] = hpack(xb2.x, xb2.y); ahB[3] = hpack(xb3.x, xb3.y);
            const uint4* wk = WF + U_AT1 + (kk + 4) * 256 + lane;
#pragma unroll
            for (int nn = 0; nn < 8; nn++) {
                uint4 w = wk[nn * 32];
                mma2(D0[nn], ahA, w);
                mma2(D1[nn], ahB, w);
            }
        }
        bias_act(D0, (const float2*)(sm + F_BA1), t, true);
        bias_act(D1, (const float2*)(sm + F_BA1), t, true);

#pragma unroll
        for (int nn = 0; nn < 8; nn++) {
            C0[nn] = make_float4(0.f, 0.f, 0.f, 0.f);
            C1[nn] = make_float4(0.f, 0.f, 0.f, 0.f);
        }
        gemm2_fromC(D0, D1, WF + U_AT2, lane, C0, C1);
        bias_act(C0, (const float2*)(sm + F_BA2), t, true);
        bias_act(C1, (const float2*)(sm + F_BA2), t, true);

        // ---- scores
        const float2* w32 = (const float2*)(sm + F_W3);
        float sA0 = 0.f, sA1 = 0.f, sB0 = 0.f, sB1 = 0.f;
#pragma unroll
        for (int nn = 0; nn < 8; nn++) {
            float2 w = w32[nn * 4 + t];
            sA0 += C0[nn].x * w.x + C0[nn].y * w.y;
            sA1 += C0[nn].z * w.x + C0[nn].w * w.y;
            sB0 += C1[nn].x * w.x + C1[nn].y * w.y;
            sB1 += C1[nn].z * w.x + C1[nn].w * w.y;
        }
        sA0 += __shfl_xor_sync(FULLMASK, sA0, 1); sA0 += __shfl_xor_sync(FULLMASK, sA0, 2);
        sA1 += __shfl_xor_sync(FULLMASK, sA1, 1); sA1 += __shfl_xor_sync(FULLMASK, sA1, 2);
        sB0 += __shfl_xor_sync(FULLMASK, sB0, 1); sB0 += __shfl_xor_sync(FULLMASK, sB0, 2);
        sB1 += __shfl_xor_sync(FULLMASK, sB1, 1); sB1 += __shfl_xor_sync(FULLMASK, sB1, 2);
        if (t == 0) {
            g_scores[row0 + g]      = sA0 + b3;
            g_scores[row0 + 8 + g]  = sA1 + b3;
            g_scores[row0 + 16 + g] = sB0 + b3;
            g_scores[row0 + 24 + g] = sB1 + b3;
        }
    }
}

// ---------------- K2: softmax + aggregation + combine MLP -------------------
__device__ __forceinline__ float wredmax(float v) {
#pragma unroll
    for (int o = 16; o; o >>= 1) v = fmaxf(v, __shfl_xor_sync(FULLMASK, v, o));
    return v;
}
__device__ __forceinline__ float wredsum(float v) {
#pragma unroll
    for (int o = 16; o; o >>= 1) v += __shfl_xor_sync(FULLMASK, v, o);
    return v;
}
constexpr int AGG_WARPS = 16;
constexpr int OFF_W1  = 0;
constexpr int OFF_W2  = 8192;
constexpr int OFF_B1  = 12288;
constexpr int OFF_B2  = 12352;
constexpr int OFF_XB2 = 12416;
constexpr int OFF_MU  = OFF_XB2 + AGG_WARPS * 128;
constexpr int SMEM2_FLOATS = OFF_MU + AGG_WARPS * 64;

template <int K, bool RELU>
__device__ __forceinline__ void mlp1(const float* __restrict__ W,
                                     const float* __restrict__ bias,
                                     const float* __restrict__ xb, int lane,
                                     float& o0, float& o1) {
    float c0 = 0.f, c1 = 0.f;
#pragma unroll 8
    for (int k = 0; k < K; k++) {
        float x = xb[k];
        c0 = fmaf(x, W[k * Dm + lane], c0);
        c1 = fmaf(x, W[k * Dm + lane + 32], c1);
    }
    c0 += bias[lane]; c1 += bias[lane + 32];
    if (RELU) { c0 = fmaxf(c0, 0.f); c1 = fmaxf(c1, 0.f); }
    o0 = c0; o1 = c1;
}

__global__ __launch_bounds__(32 * AGG_WARPS, 2)
void k_agg(const int* __restrict__ nodes_v, const float* __restrict__ embed_i,
           const float* __restrict__ w1, const float* __restrict__ b1,
           const float* __restrict__ w2, const float* __restrict__ b2,
           float* __restrict__ out) {
    extern __shared__ float smf[];
    cpf(smf + OFF_W1, w1, 8192);
    cpf(smf + OFF_W2, w2, 4096);
    cpf(smf + OFF_B1, b1, 64);
    cpf(smf + OFF_B2, b2, 64);
    __syncthreads();

    const int wid  = threadIdx.x >> 5;
    const int lane = threadIdx.x & 31;
    float* xb = smf + OFF_XB2 + wid * 128;
    float* mu = smf + OFF_MU  + wid * 64;

    for (int b = blockIdx.x * AGG_WARPS + wid; b < Bsz; b += gridDim.x * AGG_WARPS) {
        const float* sc = g_scores + b * Ln;
        float s0 = (lane < Ln)        ? sc[lane]      : -1e30f;
        float s1 = ((lane + 32) < Ln) ? sc[lane + 32] : -1e30f;
        float m  = wredmax(fmaxf(s0, s1));
        float e0 = (lane < Ln)        ? expf(s0 - m) : 0.f;
        float e1 = ((lane + 32) < Ln) ? expf(s1 - m) : 0.f;
        float inv = 1.f / wredsum(e0 + e1);
        mu[lane]      = e0 * inv;
        mu[lane + 32] = e1 * inv;
        __syncwarp();

        // zj from fp16-packed fjt: 1 LDG.32 + cvt per l
        float ax = 0.f, ay = 0.f;
        const uint32_t* fj = g_fjt_h + (size_t)b * Ln * 32;
#pragma unroll 10
        for (int l = 0; l < Ln; l++) {
            float mm = mu[l];
            uint32_t v = fj[l * 32 + lane];
            float2 f = __half22float2(*reinterpret_cast<const __half2*>(&v));
            ax = fmaf(mm, f.x, ax);
            ay = fmaf(mm, f.y, ay);
        }
        ((float2*)xb)[lane] = make_float2(ax, ay);
        int iv = nodes_v[b];
        ((float2*)(xb + 64))[lane] = ((const float2*)embed_i)[iv * 32 + lane];
        __syncwarp();

        float z0, z1;
        mlp1<128, true>(smf + OFF_W1, smf + OFF_B1, xb, lane, z0, z1);
        __syncwarp();
        xb[lane]      = z0;
        xb[lane + 32] = z1;
        __syncwarp();
        float o0, o1;
        mlp1<64, true>(smf + OFF_W2, smf + OFF_B2, xb, lane, o0, o1);
        out[b * Dm + lane]      = o0;
        out[b * Dm + lane + 32] = o1;
        __syncwarp();
    }
}

// ---------------- launch ----------------------------------------------------
extern "C" void kernel_launch(void* const* d_in, const int* in_sizes, int n_in,
                              void* d_out, int out_size) {
    const int*   nodes_v = (const int*)d_in[0];
    const int*   neigh_u = (const int*)d_in[1];
    const int*   neigh_r = (const int*)d_in[2];
    const float* embed_u = (const float*)d_in[3];
    const float* embed_i = (const float*)d_in[4];
    const float* embed_r = (const float*)d_in[5];
    const float* gv_w1 = (const float*)d_in[6];
    const float* gv_b1 = (const float*)d_in[7];
    const float* gv_w2 = (const float*)d_in[8];
    const float* gv_b2 = (const float*)d_in[9];
    const float* gv_w3 = (const float*)d_in[10];
    const float* gv_b3 = (const float*)d_in[11];
    const float* at_w1 = (const float*)d_in[12];
    const float* at_b1 = (const float*)d_in[13];
    const float* at_w2 = (const float*)d_in[14];
    const float* at_b2 = (const float*)d_in[15];
    const float* at_w3 = (const float*)d_in[16];
    const float* at_b3 = (const float*)d_in[17];
    const float* wr1_w = (const float*)d_in[18];
    const float* wr1_b = (const float*)d_in[19];
    const float* wr2_w = (const float*)d_in[20];
    const float* wr2_b = (const float*)d_in[21];
    float* out = (float*)d_out;

    int nsm = 148;
    cudaDeviceGetAttribute(&nsm, cudaDevAttrMultiProcessorCount, 0);

    const size_t s1 = SMEM1_FLOATS * sizeof(float);
    const size_t s2 = SMEM2_FLOATS * sizeof(float);
    cudaFuncSetAttribute(k_rows, cudaFuncAttributeMaxDynamicSharedMemorySize, (int)s1);
    cudaFuncSetAttribute(k_agg,  cudaFuncAttributeMaxDynamicSharedMemorySize, (int)s2);

    k_rows<<<nsm, 32 * WARPS, s1>>>(nodes_v, neigh_u, neigh_r,
                                    embed_u, embed_i, embed_r,
                                    gv_w1, gv_b1, gv_w2, gv_b2, gv_w3, gv_b3,
                                    at_w1, at_b1, at_w2, at_b2, at_w3, at_b3);
    k_agg<<<2 * nsm, 32 * AGG_WARPS, s2>>>(nodes_v, embed_i,
                                           wr1_w, wr1_b, wr2_w, wr2_b, out);
}

// round 13
// speedup vs baseline: 1.8327x; 1.0094x over previous
#include <cuda_runtime.h>
#include <cuda_fp16.h>
#include <cstdint>

#define FULLMASK 0xffffffffu

constexpr int Bsz  = 4096;
constexpr int Ln   = 50;
constexpr int Dm   = 64;
constexpr int ROWS = Bsz * Ln;       // 204800
constexpr int NUNIT = ROWS / 32;     // 6400 32-row units
constexpr int WARPS = 12;

// ---------------- scratch ---------------------------------------------------
__device__ uint32_t g_fjt_h[ROWS * 32];   // fp16x2 packed fjt [row][colpair]
__device__ float g_scores[ROWS];

// ---------------- smem float offsets (k_rows) -------------------------------
constexpr int F_WF  = 0;                  // 28672 floats (7168 uint4)
constexpr int F_ERT = 28672;              // embed_r fp16 LUT (80 uint2)
constexpr int F_B1  = 28992;
constexpr int F_B2  = 29056;
constexpr int F_B3  = 29120;
constexpr int F_BA1 = 29184;
constexpr int F_BA2 = 29248;
constexpr int F_W3  = 29312;
constexpr int F_B3S = 29376;
constexpr int SMEM1_FLOATS = 29380;
constexpr int U_GV1 = 0, U_GV2 = 2048, U_GV3 = 3072, U_AT1 = 4096, U_AT2 = 6144;

// ---------------- helpers ---------------------------------------------------
__device__ __forceinline__ void cpf(float* dst, const float* __restrict__ src, int n) {
    for (int i = threadIdx.x; i < n; i += blockDim.x) dst[i] = src[i];
}
__device__ __forceinline__ uint32_t hpack(float x0, float x1) {
    uint32_t r;
    asm("cvt.rn.f16x2.f32 %0, %1, %2;" : "=r"(r) : "f"(x1), "f"(x0));
    return r;
}
__device__ __forceinline__ void hsplit(float x0, float x1, uint32_t& hi, uint32_t& lo) {
    hi = hpack(x0, x1);
    __half2 h = *reinterpret_cast<__half2*>(&hi);
    float2 f = __half22float2(h);
    lo = hpack(x0 - f.x, x1 - f.y);
}
__device__ __forceinline__ void mma16816(float4& c, const uint32_t a[4],
                                         uint32_t b0, uint32_t b1) {
    asm volatile(
        "mma.sync.aligned.m16n8k16.row.col.f32.f16.f16.f32 "
        "{%0,%1,%2,%3}, {%4,%5,%6,%7}, {%8,%9}, {%0,%1,%2,%3};\n"
        : "+f"(c.x), "+f"(c.y), "+f"(c.z), "+f"(c.w)
        : "r"(a[0]), "r"(a[1]), "r"(a[2]), "r"(a[3]), "r"(b0), "r"(b1));
}
// 2-term: C += A*Whi + A*Wlo  (w = {hi01, hi89, lo01, lo89})
__device__ __forceinline__ void mma2(float4& c, const uint32_t ah[4], uint4 w) {
    mma16816(c, ah, w.x, w.y);
    mma16816(c, ah, w.z, w.w);
}

// weights [K x 64] -> B-fragment order {hi01, hi89, lo01, lo89} (fp16 split)
__device__ void stage_w(uint4* dst, const float* __restrict__ W, int KSTEPS) {
    int total = KSTEPS * 256;
    for (int i = threadIdx.x; i < total; i += blockDim.x) {
        int kk = i >> 8, rem = i & 255, nn = rem >> 5, lane = rem & 31;
        int g = lane >> 2, t2 = (lane & 3) * 2;
        int col = nn * 8 + g;
        int k0 = kk * 16 + t2;
        uint4 e;
        hsplit(W[k0 * 64 + col], W[(k0 + 1) * 64 + col], e.x, e.z);
        hsplit(W[(k0 + 8) * 64 + col], W[(k0 + 9) * 64 + col], e.y, e.w);
        dst[i] = e;
    }
}

__device__ __forceinline__ void bias_act(float4 C[8], const float2* __restrict__ b2,
                                         int t, bool relu) {
#pragma unroll
    for (int nn = 0; nn < 8; nn++) {
        float2 b = b2[nn * 4 + t];
        C[nn].x += b.x; C[nn].y += b.y; C[nn].z += b.x; C[nn].w += b.y;
        if (relu) {
            C[nn].x = fmaxf(C[nn].x, 0.f); C[nn].y = fmaxf(C[nn].y, 0.f);
            C[nn].z = fmaxf(C[nn].z, 0.f); C[nn].w = fmaxf(C[nn].w, 0.f);
        }
    }
}

__device__ __forceinline__ void afrag_fromC(const float4& u, const float4& v,
                                            uint32_t ah[4]) {
    ah[0] = hpack(u.x, u.y);
    ah[1] = hpack(u.z, u.w);
    ah[2] = hpack(v.x, v.y);
    ah[3] = hpack(v.z, v.w);
}

// raw 8x float2 for one k-step across 4 row-group pointers
struct Raw {
    float2 a0, a1, a2, a3, b0, b1, b2, b3;
};
__device__ __forceinline__ Raw ld_rows(const float* __restrict__ e0,
                                       const float* __restrict__ e1,
                                       const float* __restrict__ e2,
                                       const float* __restrict__ e3, int c) {
    Raw r;
    r.a0 = *(const float2*)(e0 + c);
    r.a1 = *(const float2*)(e1 + c);
    r.a2 = *(const float2*)(e0 + c + 8);
    r.a3 = *(const float2*)(e1 + c + 8);
    r.b0 = *(const float2*)(e2 + c);
    r.b1 = *(const float2*)(e3 + c);
    r.b2 = *(const float2*)(e2 + c + 8);
    r.b3 = *(const float2*)(e3 + c + 8);
    return r;
}
__device__ __forceinline__ void cvt_raw(const Raw& r, uint32_t ahA[4], uint32_t ahB[4]) {
    ahA[0] = hpack(r.a0.x, r.a0.y); ahA[1] = hpack(r.a1.x, r.a1.y);
    ahA[2] = hpack(r.a2.x, r.a2.y); ahA[3] = hpack(r.a3.x, r.a3.y);
    ahB[0] = hpack(r.b0.x, r.b0.y); ahB[1] = hpack(r.b1.x, r.b1.y);
    ahB[2] = hpack(r.b2.x, r.b2.y); ahB[3] = hpack(r.b3.x, r.b3.y);
}

__device__ __forceinline__ void mma_kk(const uint4* __restrict__ wk,
                                       const uint32_t ahA[4], const uint32_t ahB[4],
                                       float4 C0[8], float4 C1[8]) {
#pragma unroll
    for (int nn = 0; nn < 8; nn++) {
        uint4 w = wk[nn * 32];
        mma2(C0[nn], ahA, w);
        mma2(C1[nn], ahB, w);
    }
}

// dual-half fromC GEMM (K=64)
__device__ __forceinline__ void gemm2_fromC(const float4 P0[8], const float4 P1[8],
                                            const uint4* __restrict__ WK, int lane,
                                            float4 C0[8], float4 C1[8]) {
#pragma unroll
    for (int kk = 0; kk < 4; kk++) {
        uint32_t ahA[4], ahB[4];
        afrag_fromC(P0[2 * kk], P0[2 * kk + 1], ahA);
        afrag_fromC(P1[2 * kk], P1[2 * kk + 1], ahB);
        mma_kk(WK + kk * 256 + lane, ahA, ahB, C0, C1);
    }
}

// ---------------- K1: fused row MLPs, M=32/warp, fp16 2-term ----------------
__global__ __launch_bounds__(32 * WARPS, 1)
void k_rows(const int* __restrict__ nodes_v, const int* __restrict__ neigh_u,
            const int* __restrict__ neigh_r,
            const float* __restrict__ embed_u, const float* __restrict__ embed_i,
            const float* __restrict__ embed_r,
            const float* __restrict__ gw1, const float* __restrict__ gb1,
            const float* __restrict__ gw2, const float* __restrict__ gb2,
            const float* __restrict__ gw3, const float* __restrict__ gb3,
            const float* __restrict__ aw1, const float* __restrict__ ab1,
            const float* __restrict__ aw2, const float* __restrict__ ab2,
            const float* __restrict__ aw3, const float* __restrict__ ab3) {
    extern __shared__ float sm[];
    uint4* WF = reinterpret_cast<uint4*>(sm + F_WF);
    uint2* ERT = reinterpret_cast<uint2*>(sm + F_ERT);
    stage_w(WF + U_GV1, gw1, 8);
    stage_w(WF + U_GV2, gw2, 4);
    stage_w(WF + U_GV3, gw3, 4);
    stage_w(WF + U_AT1, aw1, 8);
    stage_w(WF + U_AT2, aw2, 4);
    for (int i = threadIdx.x; i < 80; i += blockDim.x) {
        int rr = i >> 4, kk = (i >> 2) & 3, t = i & 3;
        int c = kk * 16 + t * 2;
        const float* er = embed_r + rr * 64;
        uint2 e;
        e.x = hpack(er[c], er[c + 1]);
        e.y = hpack(er[c + 8], er[c + 9]);
        ERT[i] = e;
    }
    cpf(sm + F_B1,  gb1, 64);
    cpf(sm + F_B2,  gb2, 64);
    cpf(sm + F_B3,  gb3, 64);
    cpf(sm + F_BA1, ab1, 64);
    cpf(sm + F_BA2, ab2, 64);
    cpf(sm + F_W3,  aw3, 64);
    if (threadIdx.x == 0) sm[F_B3S] = ab3[0];
    __syncthreads();

    const int wid  = threadIdx.x >> 5;
    const int lane = threadIdx.x & 31;
    const int g    = lane >> 2;
    const int t    = lane & 3;
    const int t2   = t * 2;
    const float b3 = sm[F_B3S];

    const int wg      = blockIdx.x * WARPS + wid;
    const int wstride = gridDim.x * WARPS;

    for (int unit = wg; unit < NUNIT; unit += wstride) {
        const int row0 = unit * 32;
        int u0 = neigh_u[row0 + g],      u1 = neigh_u[row0 + 8 + g];
        int u2 = neigh_u[row0 + 16 + g], u3 = neigh_u[row0 + 24 + g];
        int r0i = neigh_r[row0 + g],      r1i = neigh_r[row0 + 8 + g];
        int r2i = neigh_r[row0 + 16 + g], r3i = neigh_r[row0 + 24 + g];
        const float* eu0 = embed_u + (size_t)u0 * 64;
        const float* eu1 = embed_u + (size_t)u1 * 64;
        const float* eu2 = embed_u + (size_t)u2 * 64;
        const float* eu3 = embed_u + (size_t)u3 * 64;

        float4 C0[8] = {}, C1[8] = {};
        // ---- gv1 pt phase: staged depth-2 pipeline over 4 k-steps
        {
            Raw r0 = ld_rows(eu0, eu1, eu2, eu3, t2);
            Raw r1 = ld_rows(eu0, eu1, eu2, eu3, 16 + t2);
            uint32_t A0[4], B0[4], A1[4], B1[4];
            cvt_raw(r0, A0, B0);
            cvt_raw(r1, A1, B1);
            Raw r2 = ld_rows(eu0, eu1, eu2, eu3, 32 + t2);
            Raw r3 = ld_rows(eu0, eu1, eu2, eu3, 48 + t2);
            mma_kk(WF + U_GV1 + 0 * 256 + lane, A0, B0, C0, C1);
            mma_kk(WF + U_GV1 + 1 * 256 + lane, A1, B1, C0, C1);
            cvt_raw(r2, A0, B0);
            cvt_raw(r3, A1, B1);
            mma_kk(WF + U_GV1 + 2 * 256 + lane, A0, B0, C0, C1);
            mma_kk(WF + U_GV1 + 3 * 256 + lane, A1, B1, C0, C1);
        }
        // ---- gv1, k-steps 4..7 (er from smem LUT)
#pragma unroll
        for (int kk = 0; kk < 4; kk++) {
            uint2 eA0 = ERT[(r0i * 4 + kk) * 4 + t];
            uint2 eA1 = ERT[(r1i * 4 + kk) * 4 + t];
            uint2 eB0 = ERT[(r2i * 4 + kk) * 4 + t];
            uint2 eB1 = ERT[(r3i * 4 + kk) * 4 + t];
            uint32_t ahA[4] = {eA0.x, eA1.x, eA0.y, eA1.y};
            uint32_t ahB[4] = {eB0.x, eB1.x, eB0.y, eB1.y};
            mma_kk(WF + U_GV1 + (kk + 4) * 256 + lane, ahA, ahB, C0, C1);
        }
        bias_act(C0, (const float2*)(sm + F_B1), t, true);
        bias_act(C1, (const float2*)(sm + F_B1), t, true);

        float4 D0[8] = {}, D1[8] = {};
        gemm2_fromC(C0, C1, WF + U_GV2, lane, D0, D1);
        bias_act(D0, (const float2*)(sm + F_B2), t, true);
        bias_act(D1, (const float2*)(sm + F_B2), t, true);

#pragma unroll
        for (int nn = 0; nn < 8; nn++) {
            C0[nn] = make_float4(0.f, 0.f, 0.f, 0.f);
            C1[nn] = make_float4(0.f, 0.f, 0.f, 0.f);
        }
        gemm2_fromC(D0, D1, WF + U_GV3, lane, C0, C1);
        bias_act(C0, (const float2*)(sm + F_B3), t, false);
        bias_act(C1, (const float2*)(sm + F_B3), t, false);   // C = fjt frags

        // ---- fjt -> global as fp16x2
#pragma unroll
        for (int nn = 0; nn < 8; nn++) {
            int c4 = nn * 4 + t;
            g_fjt_h[(row0 + g) * 32 + c4]      = hpack(C0[nn].x, C0[nn].y);
            g_fjt_h[(row0 + 8 + g) * 32 + c4]  = hpack(C0[nn].z, C0[nn].w);
            g_fjt_h[(row0 + 16 + g) * 32 + c4] = hpack(C1[nn].x, C1[nn].y);
            g_fjt_h[(row0 + 24 + g) * 32 + c4] = hpack(C1[nn].z, C1[nn].w);
        }

        // ---- qj row pointers (<=2 distinct b per 32-row unit)
        int b0i = row0 / Ln;
        int rof = row0 - b0i * Ln;
        int nv0 = nodes_v[b0i];
        int nv1 = nodes_v[(b0i + 1 < Bsz) ? b0i + 1 : Bsz - 1];
        const float* ei0 = embed_i + (size_t)((rof + g      >= Ln) ? nv1 : nv0) * 64;
        const float* ei1 = embed_i + (size_t)((rof + 8 + g  >= Ln) ? nv1 : nv0) * 64;
        const float* ei2 = embed_i + (size_t)((rof + 16 + g >= Ln) ? nv1 : nv0) * 64;
        const float* ei3 = embed_i + (size_t)((rof + 24 + g >= Ln) ? nv1 : nv0) * 64;

        // ---- at1: fromC k-steps interleaved with qj load issue
#pragma unroll
        for (int nn = 0; nn < 8; nn++) {
            D0[nn] = make_float4(0.f, 0.f, 0.f, 0.f);
            D1[nn] = make_float4(0.f, 0.f, 0.f, 0.f);
        }
        {
            // fromC kk 0,1 (frees C[0..3])
#pragma unroll
            for (int kk = 0; kk < 2; kk++) {
                uint32_t ahA[4], ahB[4];
                afrag_fromC(C0[2 * kk], C0[2 * kk + 1], ahA);
                afrag_fromC(C1[2 * kk], C1[2 * kk + 1], ahB);
                mma_kk(WF + U_AT1 + kk * 256 + lane, ahA, ahB, D0, D1);
            }
            // issue qj loads for k-steps 4,5 while fromC kk 2,3 runs
            Raw q0 = ld_rows(ei0, ei1, ei2, ei3, t2);
            Raw q1 = ld_rows(ei0, ei1, ei2, ei3, 16 + t2);
#pragma unroll
            for (int kk = 2; kk < 4; kk++) {
                uint32_t ahA[4], ahB[4];
                afrag_fromC(C0[2 * kk], C0[2 * kk + 1], ahA);
                afrag_fromC(C1[2 * kk], C1[2 * kk + 1], ahB);
                mma_kk(WF + U_AT1 + kk * 256 + lane, ahA, ahB, D0, D1);
            }
            uint32_t A0[4], B0[4], A1[4], B1[4];
            cvt_raw(q0, A0, B0);
            cvt_raw(q1, A1, B1);
            Raw q2 = ld_rows(ei0, ei1, ei2, ei3, 32 + t2);
            Raw q3 = ld_rows(ei0, ei1, ei2, ei3, 48 + t2);
            mma_kk(WF + U_AT1 + 4 * 256 + lane, A0, B0, D0, D1);
            mma_kk(WF + U_AT1 + 5 * 256 + lane, A1, B1, D0, D1);
            cvt_raw(q2, A0, B0);
            cvt_raw(q3, A1, B1);
            mma_kk(WF + U_AT1 + 6 * 256 + lane, A0, B0, D0, D1);
            mma_kk(WF + U_AT1 + 7 * 256 + lane, A1, B1, D0, D1);
        }
        bias_act(D0, (const float2*)(sm + F_BA1), t, true);
        bias_act(D1, (const float2*)(sm + F_BA1), t, true);

#pragma unroll
        for (int nn = 0; nn < 8; nn++) {
            C0[nn] = make_float4(0.f, 0.f, 0.f, 0.f);
            C1[nn] = make_float4(0.f, 0.f, 0.f, 0.f);
        }
        gemm2_fromC(D0, D1, WF + U_AT2, lane, C0, C1);
        bias_act(C0, (const float2*)(sm + F_BA2), t, true);
        bias_act(C1, (const float2*)(sm + F_BA2), t, true);

        // ---- scores
        const float2* w32 = (const float2*)(sm + F_W3);
        float sA0 = 0.f, sA1 = 0.f, sB0 = 0.f, sB1 = 0.f;
#pragma unroll
        for (int nn = 0; nn < 8; nn++) {
            float2 w = w32[nn * 4 + t];
            sA0 += C0[nn].x * w.x + C0[nn].y * w.y;
            sA1 += C0[nn].z * w.x + C0[nn].w * w.y;
            sB0 += C1[nn].x * w.x + C1[nn].y * w.y;
            sB1 += C1[nn].z * w.x + C1[nn].w * w.y;
        }
        sA0 += __shfl_xor_sync(FULLMASK, sA0, 1); sA0 += __shfl_xor_sync(FULLMASK, sA0, 2);
        sA1 += __shfl_xor_sync(FULLMASK, sA1, 1); sA1 += __shfl_xor_sync(FULLMASK, sA1, 2);
        sB0 += __shfl_xor_sync(FULLMASK, sB0, 1); sB0 += __shfl_xor_sync(FULLMASK, sB0, 2);
        sB1 += __shfl_xor_sync(FULLMASK, sB1, 1); sB1 += __shfl_xor_sync(FULLMASK, sB1, 2);
        if (t == 0) {
            g_scores[row0 + g]      = sA0 + b3;
            g_scores[row0 + 8 + g]  = sA1 + b3;
            g_scores[row0 + 16 + g] = sB0 + b3;
            g_scores[row0 + 24 + g] = sB1 + b3;
        }
    }
}

// ---------------- K2: softmax + aggregation + combine MLP -------------------
__device__ __forceinline__ float wredmax(float v) {
#pragma unroll
    for (int o = 16; o; o >>= 1) v = fmaxf(v, __shfl_xor_sync(FULLMASK, v, o));
    return v;
}
__device__ __forceinline__ float wredsum(float v) {
#pragma unroll
    for (int o = 16; o; o >>= 1) v += __shfl_xor_sync(FULLMASK, v, o);
    return v;
}
constexpr int AGG_WARPS = 16;
constexpr int AGG_GRID  = 256;                 // 4096 warps -> 1 b each, one wave
constexpr int OFF_W1  = 0;                     // paired: 4096 float2 = 8192 floats
constexpr int OFF_W2  = 8192;                  // paired: 2048 float2 = 4096 floats
constexpr int OFF_B1  = 12288;
constexpr int OFF_B2  = 12352;
constexpr int OFF_XB2 = 12416;
constexpr int OFF_MU  = OFF_XB2 + AGG_WARPS * 128;
constexpr int SMEM2_FLOATS = OFF_MU + AGG_WARPS * 64;

// pair columns j, j+32 into float2
__device__ __forceinline__ void cpf_pair(float2* dst, const float* __restrict__ W, int K) {
    for (int i = threadIdx.x; i < K * 32; i += blockDim.x) {
        int k = i >> 5, j = i & 31;
        dst[i] = make_float2(W[k * 64 + j], W[k * 64 + j + 32]);
    }
}

template <int K, bool RELU>
__device__ __forceinline__ void mlp1p(const float2* __restrict__ Wp,
                                      const float* __restrict__ bias,
                                      const float* __restrict__ xb, int lane,
                                      float& o0, float& o1) {
    float c0 = 0.f, c1 = 0.f;
#pragma unroll 8
    for (int k = 0; k < K; k++) {
        float x = xb[k];
        float2 w = Wp[k * 32 + lane];
        c0 = fmaf(x, w.x, c0);
        c1 = fmaf(x, w.y, c1);
    }
    c0 += bias[lane]; c1 += bias[lane + 32];
    if (RELU) { c0 = fmaxf(c0, 0.f); c1 = fmaxf(c1, 0.f); }
    o0 = c0; o1 = c1;
}

__global__ __launch_bounds__(32 * AGG_WARPS, 2)
void k_agg(const int* __restrict__ nodes_v, const float* __restrict__ embed_i,
           const float* __restrict__ w1, const float* __restrict__ b1,
           const float* __restrict__ w2, const float* __restrict__ b2,
           float* __restrict__ out) {
    extern __shared__ float smf[];
    cpf_pair((float2*)(smf + OFF_W1), w1, 128);
    cpf_pair((float2*)(smf + OFF_W2), w2, 64);
    cpf(smf + OFF_B1, b1, 64);
    cpf(smf + OFF_B2, b2, 64);
    __syncthreads();

    const int wid  = threadIdx.x >> 5;
    const int lane = threadIdx.x & 31;
    float* xb = smf + OFF_XB2 + wid * 128;
    float* mu = smf + OFF_MU  + wid * 64;

    for (int b = blockIdx.x * AGG_WARPS + wid; b < Bsz; b += gridDim.x * AGG_WARPS) {
        const float* sc = g_scores + b * Ln;
        float s0 = (lane < Ln)        ? sc[lane]      : -1e30f;
        float s1 = ((lane + 32) < Ln) ? sc[lane + 32] : -1e30f;
        float m  = wredmax(fmaxf(s0, s1));
        float e0 = (lane < Ln)        ? expf(s0 - m) : 0.f;
        float e1 = ((lane + 32) < Ln) ? expf(s1 - m) : 0.f;
        float inv = 1.f / wredsum(e0 + e1);
        mu[lane]      = e0 * inv;
        mu[lane + 32] = e1 * inv;
        __syncwarp();

        float ax = 0.f, ay = 0.f;
        const uint32_t* fj = g_fjt_h + (size_t)b * Ln * 32;
#pragma unroll 10
        for (int l = 0; l < Ln; l++) {
            float mm = mu[l];
            uint32_t v = fj[l * 32 + lane];
            float2 f = __half22float2(*reinterpret_cast<const __half2*>(&v));
            ax = fmaf(mm, f.x, ax);
            ay = fmaf(mm, f.y, ay);
        }
        ((float2*)xb)[lane] = make_float2(ax, ay);
        int iv = nodes_v[b];
        ((float2*)(xb + 64))[lane] = ((const float2*)embed_i)[iv * 32 + lane];
        __syncwarp();

        float z0, z1;
        mlp1p<128, true>((const float2*)(smf + OFF_W1), smf + OFF_B1, xb, lane, z0, z1);
        __syncwarp();
        xb[lane]      = z0;
        xb[lane + 32] = z1;
        __syncwarp();
        float o0, o1;
        mlp1p<64, true>((const float2*)(smf + OFF_W2), smf + OFF_B2, xb, lane, o0, o1);
        out[b * Dm + lane]      = o0;
        out[b * Dm + lane + 32] = o1;
        __syncwarp();
    }
}

// ---------------- launch ----------------------------------------------------
extern "C" void kernel_launch(void* const* d_in, const int* in_sizes, int n_in,
                              void* d_out, int out_size) {
    const int*   nodes_v = (const int*)d_in[0];
    const int*   neigh_u = (const int*)d_in[1];
    const int*   neigh_r = (const int*)d_in[2];
    const float* embed_u = (const float*)d_in[3];
    const float* embed_i = (const float*)d_in[4];
    const float* embed_r = (const float*)d_in[5];
    const float* gv_w1 = (const float*)d_in[6];
    const float* gv_b1 = (const float*)d_in[7];
    const float* gv_w2 = (const float*)d_in[8];
    const float* gv_b2 = (const float*)d_in[9];
    const float* gv_w3 = (const float*)d_in[10];
    const float* gv_b3 = (const float*)d_in[11];
    const float* at_w1 = (const float*)d_in[12];
    const float* at_b1 = (const float*)d_in[13];
    const float* at_w2 = (const float*)d_in[14];
    const float* at_b2 = (const float*)d_in[15];
    const float* at_w3 = (const float*)d_in[16];
    const float* at_b3 = (const float*)d_in[17];
    const float* wr1_w = (const float*)d_in[18];
    const float* wr1_b = (const float*)d_in[19];
    const float* wr2_w = (const float*)d_in[20];
    const float* wr2_b = (const float*)d_in[21];
    float* out = (float*)d_out;

    int nsm = 148;
    cudaDeviceGetAttribute(&nsm, cudaDevAttrMultiProcessorCount, 0);

    const size_t s1 = SMEM1_FLOATS * sizeof(float);
    const size_t s2 = SMEM2_FLOATS * sizeof(float);
    cudaFuncSetAttribute(k_rows, cudaFuncAttributeMaxDynamicSharedMemorySize, (int)s1);
    cudaFuncSetAttribute(k_agg,  cudaFuncAttributeMaxDynamicSharedMemorySize, (int)s2);

    k_rows<<<nsm, 32 * WARPS, s1>>>(nodes_v, neigh_u, neigh_r,
                                    embed_u, embed_i, embed_r,
                                    gv_w1, gv_b1, gv_w2, gv_b2, gv_w3, gv_b3,
                                    at_w1, at_b1, at_w2, at_b2, at_w3, at_b3);
    k_agg<<<AGG_GRID, 32 * AGG_WARPS, s2>>>(nodes_v, embed_i,
                                            wr1_w, wr1_b, wr2_w, wr2_b, out);
}

// round 14
// speedup vs baseline: 2.4628x; 1.3439x over previous
#include <cuda_runtime.h>
#include <cuda_fp16.h>
#include <cstdint>

#define FULLMASK 0xffffffffu

constexpr int Bsz  = 4096;
constexpr int Ln   = 50;
constexpr int Dm   = 64;
constexpr int ROWS = Bsz * Ln;       // 204800
constexpr int NUNIT = ROWS / 32;     // 6400 32-row units
constexpr int WARPS = 12;

// ---------------- scratch ---------------------------------------------------
__device__ uint32_t g_fjt_h[ROWS * 32];   // fp16x2 packed fjt [row][colpair]
__device__ float g_scores[ROWS];

// ---------------- smem float offsets (k_rows) -------------------------------
// WF: 7168 uint2 (gv1 2048 | gv2 1024 | gv3 1024 | at1 2048 | at2 1024) = 14336 floats
constexpr int F_WF  = 0;
constexpr int F_ERT = 14336;              // embed_r fp16 LUT (80 uint2 = 160 floats)
constexpr int F_B1  = 14496;
constexpr int F_B2  = 14560;
constexpr int F_B3  = 14624;
constexpr int F_BA1 = 14688;
constexpr int F_BA2 = 14752;
constexpr int F_W3  = 14816;
constexpr int F_B3S = 14880;
constexpr int SMEM1_FLOATS = 14884;       // ~59.5 KB
constexpr int U_GV1 = 0, U_GV2 = 2048, U_GV3 = 3072, U_AT1 = 4096, U_AT2 = 6144;

// ---------------- helpers ---------------------------------------------------
__device__ __forceinline__ void cpf(float* dst, const float* __restrict__ src, int n) {
    for (int i = threadIdx.x; i < n; i += blockDim.x) dst[i] = src[i];
}
__device__ __forceinline__ uint32_t hpack(float x0, float x1) {
    uint32_t r;
    asm("cvt.rn.f16x2.f32 %0, %1, %2;" : "=r"(r) : "f"(x1), "f"(x0));
    return r;
}
__device__ __forceinline__ void mma16816(float4& c, const uint32_t a[4],
                                         uint32_t b0, uint32_t b1) {
    asm volatile(
        "mma.sync.aligned.m16n8k16.row.col.f32.f16.f16.f32 "
        "{%0,%1,%2,%3}, {%4,%5,%6,%7}, {%8,%9}, {%0,%1,%2,%3};\n"
        : "+f"(c.x), "+f"(c.y), "+f"(c.z), "+f"(c.w)
        : "r"(a[0]), "r"(a[1]), "r"(a[2]), "r"(a[3]), "r"(b0), "r"(b1));
}

// weights [K x 64] -> B-fragment order {hi01, hi89} (single fp16, 1 mma/kk)
__device__ void stage_w(uint2* dst, const float* __restrict__ W, int KSTEPS) {
    int total = KSTEPS * 256;
    for (int i = threadIdx.x; i < total; i += blockDim.x) {
        int kk = i >> 8, rem = i & 255, nn = rem >> 5, lane = rem & 31;
        int g = lane >> 2, t2 = (lane & 3) * 2;
        int col = nn * 8 + g;
        int k0 = kk * 16 + t2;
        uint2 e;
        e.x = hpack(W[k0 * 64 + col], W[(k0 + 1) * 64 + col]);
        e.y = hpack(W[(k0 + 8) * 64 + col], W[(k0 + 9) * 64 + col]);
        dst[i] = e;
    }
}

__device__ __forceinline__ void bias_act(float4 C[8], const float2* __restrict__ b2,
                                         int t, bool relu) {
#pragma unroll
    for (int nn = 0; nn < 8; nn++) {
        float2 b = b2[nn * 4 + t];
        C[nn].x += b.x; C[nn].y += b.y; C[nn].z += b.x; C[nn].w += b.y;
        if (relu) {
            C[nn].x = fmaxf(C[nn].x, 0.f); C[nn].y = fmaxf(C[nn].y, 0.f);
            C[nn].z = fmaxf(C[nn].z, 0.f); C[nn].w = fmaxf(C[nn].w, 0.f);
        }
    }
}

__device__ __forceinline__ void afrag_fromC(const float4& u, const float4& v,
                                            uint32_t ah[4]) {
    ah[0] = hpack(u.x, u.y);
    ah[1] = hpack(u.z, u.w);
    ah[2] = hpack(v.x, v.y);
    ah[3] = hpack(v.z, v.w);
}

// raw 8x float2 for one k-step across 4 row-group pointers
struct Raw {
    float2 a0, a1, a2, a3, b0, b1, b2, b3;
};
__device__ __forceinline__ Raw ld_rows(const float* __restrict__ e0,
                                       const float* __restrict__ e1,
                                       const float* __restrict__ e2,
                                       const float* __restrict__ e3, int c) {
    Raw r;
    r.a0 = *(const float2*)(e0 + c);
    r.a1 = *(const float2*)(e1 + c);
    r.a2 = *(const float2*)(e0 + c + 8);
    r.a3 = *(const float2*)(e1 + c + 8);
    r.b0 = *(const float2*)(e2 + c);
    r.b1 = *(const float2*)(e3 + c);
    r.b2 = *(const float2*)(e2 + c + 8);
    r.b3 = *(const float2*)(e3 + c + 8);
    return r;
}
__device__ __forceinline__ void cvt_raw(const Raw& r, uint32_t ahA[4], uint32_t ahB[4]) {
    ahA[0] = hpack(r.a0.x, r.a0.y); ahA[1] = hpack(r.a1.x, r.a1.y);
    ahA[2] = hpack(r.a2.x, r.a2.y); ahA[3] = hpack(r.a3.x, r.a3.y);
    ahB[0] = hpack(r.b0.x, r.b0.y); ahB[1] = hpack(r.b1.x, r.b1.y);
    ahB[2] = hpack(r.b2.x, r.b2.y); ahB[3] = hpack(r.b3.x, r.b3.y);
}

__device__ __forceinline__ void mma_kk(const uint2* __restrict__ wk,
                                       const uint32_t ahA[4], const uint32_t ahB[4],
                                       float4 C0[8], float4 C1[8]) {
#pragma unroll
    for (int nn = 0; nn < 8; nn++) {
        uint2 w = wk[nn * 32];
        mma16816(C0[nn], ahA, w.x, w.y);
        mma16816(C1[nn], ahB, w.x, w.y);
    }
}

// dual-half fromC GEMM (K=64)
__device__ __forceinline__ void gemm2_fromC(const float4 P0[8], const float4 P1[8],
                                            const uint2* __restrict__ WK, int lane,
                                            float4 C0[8], float4 C1[8]) {
#pragma unroll
    for (int kk = 0; kk < 4; kk++) {
        uint32_t ahA[4], ahB[4];
        afrag_fromC(P0[2 * kk], P0[2 * kk + 1], ahA);
        afrag_fromC(P1[2 * kk], P1[2 * kk + 1], ahB);
        mma_kk(WK + kk * 256 + lane, ahA, ahB, C0, C1);
    }
}

// ---------------- K1: fused row MLPs, M=32/warp, single-fp16 mma ------------
__global__ __launch_bounds__(32 * WARPS, 1)
void k_rows(const int* __restrict__ nodes_v, const int* __restrict__ neigh_u,
            const int* __restrict__ neigh_r,
            const float* __restrict__ embed_u, const float* __restrict__ embed_i,
            const float* __restrict__ embed_r,
            const float* __restrict__ gw1, const float* __restrict__ gb1,
            const float* __restrict__ gw2, const float* __restrict__ gb2,
            const float* __restrict__ gw3, const float* __restrict__ gb3,
            const float* __restrict__ aw1, const float* __restrict__ ab1,
            const float* __restrict__ aw2, const float* __restrict__ ab2,
            const float* __restrict__ aw3, const float* __restrict__ ab3) {
    extern __shared__ float sm[];
    uint2* WF = reinterpret_cast<uint2*>(sm + F_WF);
    uint2* ERT = reinterpret_cast<uint2*>(sm + F_ERT);
    stage_w(WF + U_GV1, gw1, 8);
    stage_w(WF + U_GV2, gw2, 4);
    stage_w(WF + U_GV3, gw3, 4);
    stage_w(WF + U_AT1, aw1, 8);
    stage_w(WF + U_AT2, aw2, 4);
    for (int i = threadIdx.x; i < 80; i += blockDim.x) {
        int rr = i >> 4, kk = (i >> 2) & 3, t = i & 3;
        int c = kk * 16 + t * 2;
        const float* er = embed_r + rr * 64;
        uint2 e;
        e.x = hpack(er[c], er[c + 1]);
        e.y = hpack(er[c + 8], er[c + 9]);
        ERT[i] = e;
    }
    cpf(sm + F_B1,  gb1, 64);
    cpf(sm + F_B2,  gb2, 64);
    cpf(sm + F_B3,  gb3, 64);
    cpf(sm + F_BA1, ab1, 64);
    cpf(sm + F_BA2, ab2, 64);
    cpf(sm + F_W3,  aw3, 64);
    if (threadIdx.x == 0) sm[F_B3S] = ab3[0];
    __syncthreads();

    const int wid  = threadIdx.x >> 5;
    const int lane = threadIdx.x & 31;
    const int g    = lane >> 2;
    const int t    = lane & 3;
    const int t2   = t * 2;
    const float b3 = sm[F_B3S];

    const int wg      = blockIdx.x * WARPS + wid;
    const int wstride = gridDim.x * WARPS;

    for (int unit = wg; unit < NUNIT; unit += wstride) {
        const int row0 = unit * 32;
        int u0 = neigh_u[row0 + g],      u1 = neigh_u[row0 + 8 + g];
        int u2 = neigh_u[row0 + 16 + g], u3 = neigh_u[row0 + 24 + g];
        int r0i = neigh_r[row0 + g],      r1i = neigh_r[row0 + 8 + g];
        int r2i = neigh_r[row0 + 16 + g], r3i = neigh_r[row0 + 24 + g];
        const float* eu0 = embed_u + (size_t)u0 * 64;
        const float* eu1 = embed_u + (size_t)u1 * 64;
        const float* eu2 = embed_u + (size_t)u2 * 64;
        const float* eu3 = embed_u + (size_t)u3 * 64;

        float4 C0[8] = {}, C1[8] = {};
        // ---- gv1 pt phase: staged depth-2 pipeline over 4 k-steps
        {
            Raw r0 = ld_rows(eu0, eu1, eu2, eu3, t2);
            Raw r1 = ld_rows(eu0, eu1, eu2, eu3, 16 + t2);
            uint32_t A0[4], B0[4], A1[4], B1[4];
            cvt_raw(r0, A0, B0);
            cvt_raw(r1, A1, B1);
            Raw r2 = ld_rows(eu0, eu1, eu2, eu3, 32 + t2);
            Raw r3 = ld_rows(eu0, eu1, eu2, eu3, 48 + t2);
            mma_kk(WF + U_GV1 + 0 * 256 + lane, A0, B0, C0, C1);
            mma_kk(WF + U_GV1 + 1 * 256 + lane, A1, B1, C0, C1);
            cvt_raw(r2, A0, B0);
            cvt_raw(r3, A1, B1);
            mma_kk(WF + U_GV1 + 2 * 256 + lane, A0, B0, C0, C1);
            mma_kk(WF + U_GV1 + 3 * 256 + lane, A1, B1, C0, C1);
        }
        // ---- gv1, k-steps 4..7 (er from smem LUT)
#pragma unroll
        for (int kk = 0; kk < 4; kk++) {
            uint2 eA0 = ERT[(r0i * 4 + kk) * 4 + t];
            uint2 eA1 = ERT[(r1i * 4 + kk) * 4 + t];
            uint2 eB0 = ERT[(r2i * 4 + kk) * 4 + t];
            uint2 eB1 = ERT[(r3i * 4 + kk) * 4 + t];
            uint32_t ahA[4] = {eA0.x, eA1.x, eA0.y, eA1.y};
            uint32_t ahB[4] = {eB0.x, eB1.x, eB0.y, eB1.y};
            mma_kk(WF + U_GV1 + (kk + 4) * 256 + lane, ahA, ahB, C0, C1);
        }
        bias_act(C0, (const float2*)(sm + F_B1), t, true);
        bias_act(C1, (const float2*)(sm + F_B1), t, true);

        float4 D0[8] = {}, D1[8] = {};
        gemm2_fromC(C0, C1, WF + U_GV2, lane, D0, D1);
        bias_act(D0, (const float2*)(sm + F_B2), t, true);
        bias_act(D1, (const float2*)(sm + F_B2), t, true);

#pragma unroll
        for (int nn = 0; nn < 8; nn++) {
            C0[nn] = make_float4(0.f, 0.f, 0.f, 0.f);
            C1[nn] = make_float4(0.f, 0.f, 0.f, 0.f);
        }
        gemm2_fromC(D0, D1, WF + U_GV3, lane, C0, C1);
        bias_act(C0, (const float2*)(sm + F_B3), t, false);
        bias_act(C1, (const float2*)(sm + F_B3), t, false);   // C = fjt frags

        // ---- fjt -> global as fp16x2
#pragma unroll
        for (int nn = 0; nn < 8; nn++) {
            int c4 = nn * 4 + t;
            g_fjt_h[(row0 + g) * 32 + c4]      = hpack(C0[nn].x, C0[nn].y);
            g_fjt_h[(row0 + 8 + g) * 32 + c4]  = hpack(C0[nn].z, C0[nn].w);
            g_fjt_h[(row0 + 16 + g) * 32 + c4] = hpack(C1[nn].x, C1[nn].y);
            g_fjt_h[(row0 + 24 + g) * 32 + c4] = hpack(C1[nn].z, C1[nn].w);
        }

        // ---- qj row pointers (<=2 distinct b per 32-row unit)
        int b0i = row0 / Ln;
        int rof = row0 - b0i * Ln;
        int nv0 = nodes_v[b0i];
        int nv1 = nodes_v[(b0i + 1 < Bsz) ? b0i + 1 : Bsz - 1];
        const float* ei0 = embed_i + (size_t)((rof + g      >= Ln) ? nv1 : nv0) * 64;
        const float* ei1 = embed_i + (size_t)((rof + 8 + g  >= Ln) ? nv1 : nv0) * 64;
        const float* ei2 = embed_i + (size_t)((rof + 16 + g >= Ln) ? nv1 : nv0) * 64;
        const float* ei3 = embed_i + (size_t)((rof + 24 + g >= Ln) ? nv1 : nv0) * 64;

        // ---- at1: fromC k-steps interleaved with qj load issue
#pragma unroll
        for (int nn = 0; nn < 8; nn++) {
            D0[nn] = make_float4(0.f, 0.f, 0.f, 0.f);
            D1[nn] = make_float4(0.f, 0.f, 0.f, 0.f);
        }
        {
#pragma unroll
            for (int kk = 0; kk < 2; kk++) {
                uint32_t ahA[4], ahB[4];
                afrag_fromC(C0[2 * kk], C0[2 * kk + 1], ahA);
                afrag_fromC(C1[2 * kk], C1[2 * kk + 1], ahB);
                mma_kk(WF + U_AT1 + kk * 256 + lane, ahA, ahB, D0, D1);
            }
            Raw q0 = ld_rows(ei0, ei1, ei2, ei3, t2);
            Raw q1 = ld_rows(ei0, ei1, ei2, ei3, 16 + t2);
#pragma unroll
            for (int kk = 2; kk < 4; kk++) {
                uint32_t ahA[4], ahB[4];
                afrag_fromC(C0[2 * kk], C0[2 * kk + 1], ahA);
                afrag_fromC(C1[2 * kk], C1[2 * kk + 1], ahB);
                mma_kk(WF + U_AT1 + kk * 256 + lane, ahA, ahB, D0, D1);
            }
            uint32_t A0[4], B0[4], A1[4], B1[4];
            cvt_raw(q0, A0, B0);
            cvt_raw(q1, A1, B1);
            Raw q2 = ld_rows(ei0, ei1, ei2, ei3, 32 + t2);
            Raw q3 = ld_rows(ei0, ei1, ei2, ei3, 48 + t2);
            mma_kk(WF + U_AT1 + 4 * 256 + lane, A0, B0, D0, D1);
            mma_kk(WF + U_AT1 + 5 * 256 + lane, A1, B1, D0, D1);
            cvt_raw(q2, A0, B0);
            cvt_raw(q3, A1, B1);
            mma_kk(WF + U_AT1 + 6 * 256 + lane, A0, B0, D0, D1);
            mma_kk(WF + U_AT1 + 7 * 256 + lane, A1, B1, D0, D1);
        }
        bias_act(D0, (const float2*)(sm + F_BA1), t, true);
        bias_act(D1, (const float2*)(sm + F_BA1), t, true);

#pragma unroll
        for (int nn = 0; nn < 8; nn++) {
            C0[nn] = make_float4(0.f, 0.f, 0.f, 0.f);
            C1[nn] = make_float4(0.f, 0.f, 0.f, 0.f);
        }
        gemm2_fromC(D0, D1, WF + U_AT2, lane, C0, C1);
        bias_act(C0, (const float2*)(sm + F_BA2), t, true);
        bias_act(C1, (const float2*)(sm + F_BA2), t, true);

        // ---- scores
        const float2* w32 = (const float2*)(sm + F_W3);
        float sA0 = 0.f, sA1 = 0.f, sB0 = 0.f, sB1 = 0.f;
#pragma unroll
        for (int nn = 0; nn < 8; nn++) {
            float2 w = w32[nn * 4 + t];
            sA0 += C0[nn].x * w.x + C0[nn].y * w.y;
            sA1 += C0[nn].z * w.x + C0[nn].w * w.y;
            sB0 += C1[nn].x * w.x + C1[nn].y * w.y;
            sB1 += C1[nn].z * w.x + C1[nn].w * w.y;
        }
        sA0 += __shfl_xor_sync(FULLMASK, sA0, 1); sA0 += __shfl_xor_sync(FULLMASK, sA0, 2);
        sA1 += __shfl_xor_sync(FULLMASK, sA1, 1); sA1 += __shfl_xor_sync(FULLMASK, sA1, 2);
        sB0 += __shfl_xor_sync(FULLMASK, sB0, 1); sB0 += __shfl_xor_sync(FULLMASK, sB0, 2);
        sB1 += __shfl_xor_sync(FULLMASK, sB1, 1); sB1 += __shfl_xor_sync(FULLMASK, sB1, 2);
        if (t == 0) {
            g_scores[row0 + g]      = sA0 + b3;
            g_scores[row0 + 8 + g]  = sA1 + b3;
            g_scores[row0 + 16 + g] = sB0 + b3;
            g_scores[row0 + 24 + g] = sB1 + b3;
        }
    }
}

// ---------------- K2: softmax + aggregation + combine MLP -------------------
__device__ __forceinline__ float wredmax(float v) {
#pragma unroll
    for (int o = 16; o; o >>= 1) v = fmaxf(v, __shfl_xor_sync(FULLMASK, v, o));
    return v;
}
__device__ __forceinline__ float wredsum(float v) {
#pragma unroll
    for (int o = 16; o; o >>= 1) v += __shfl_xor_sync(FULLMASK, v, o);
    return v;
}
constexpr int AGG_WARPS = 16;
constexpr int AGG_GRID  = 256;
constexpr int OFF_W1  = 0;
constexpr int OFF_W2  = 8192;
constexpr int OFF_B1  = 12288;
constexpr int OFF_B2  = 12352;
constexpr int OFF_XB2 = 12416;
constexpr int OFF_MU  = OFF_XB2 + AGG_WARPS * 128;
constexpr int SMEM2_FLOATS = OFF_MU + AGG_WARPS * 64;

__device__ __forceinline__ void cpf_pair(float2* dst, const float* __restrict__ W, int K) {
    for (int i = threadIdx.x; i < K * 32; i += blockDim.x) {
        int k = i >> 5, j = i & 31;
        dst[i] = make_float2(W[k * 64 + j], W[k * 64 + j + 32]);
    }
}

template <int K, bool RELU>
__device__ __forceinline__ void mlp1p(const float2* __restrict__ Wp,
                                      const float* __restrict__ bias,
                                      const float* __restrict__ xb, int lane,
                                      float& o0, float& o1) {
    float c0 = 0.f, c1 = 0.f;
#pragma unroll 8
    for (int k = 0; k < K; k++) {
        float x = xb[k];
        float2 w = Wp[k * 32 + lane];
        c0 = fmaf(x, w.x, c0);
        c1 = fmaf(x, w.y, c1);
    }
    c0 += bias[lane]; c1 += bias[lane + 32];
    if (RELU) { c0 = fmaxf(c0, 0.f); c1 = fmaxf(c1, 0.f); }
    o0 = c0; o1 = c1;
}

__global__ __launch_bounds__(32 * AGG_WARPS, 2)
void k_agg(const int* __restrict__ nodes_v, const float* __restrict__ embed_i,
           const float* __restrict__ w1, const float* __restrict__ b1,
           const float* __restrict__ w2, const float* __restrict__ b2,
           float* __restrict__ out) {
    extern __shared__ float smf[];
    cpf_pair((float2*)(smf + OFF_W1), w1, 128);
    cpf_pair((float2*)(smf + OFF_W2), w2, 64);
    cpf(smf + OFF_B1, b1, 64);
    cpf(smf + OFF_B2, b2, 64);
    __syncthreads();

    const int wid  = threadIdx.x >> 5;
    const int lane = threadIdx.x & 31;
    float* xb = smf + OFF_XB2 + wid * 128;
    float* mu = smf + OFF_MU  + wid * 64;

    for (int b = blockIdx.x * AGG_WARPS + wid; b < Bsz; b += gridDim.x * AGG_WARPS) {
        const float* sc = g_scores + b * Ln;
        float s0 = (lane < Ln)        ? sc[lane]      : -1e30f;
        float s1 = ((lane + 32) < Ln) ? sc[lane + 32] : -1e30f;
        float m  = wredmax(fmaxf(s0, s1));
        float e0 = (lane < Ln)        ? expf(s0 - m) : 0.f;
        float e1 = ((lane + 32) < Ln) ? expf(s1 - m) : 0.f;
        float inv = 1.f / wredsum(e0 + e1);
        mu[lane]      = e0 * inv;
        mu[lane + 32] = e1 * inv;
        __syncwarp();

        float ax = 0.f, ay = 0.f;
        const uint32_t* fj = g_fjt_h + (size_t)b * Ln * 32;
#pragma unroll 10
        for (int l = 0; l < Ln; l++) {
            float mm = mu[l];
            uint32_t v = fj[l * 32 + lane];
            float2 f = __half22float2(*reinterpret_cast<const __half2*>(&v));
            ax = fmaf(mm, f.x, ax);
            ay = fmaf(mm, f.y, ay);
        }
        ((float2*)xb)[lane] = make_float2(ax, ay);
        int iv = nodes_v[b];
        ((float2*)(xb + 64))[lane] = ((const float2*)embed_i)[iv * 32 + lane];
        __syncwarp();

        float z0, z1;
        mlp1p<128, true>((const float2*)(smf + OFF_W1), smf + OFF_B1, xb, lane, z0, z1);
        __syncwarp();
        xb[lane]      = z0;
        xb[lane + 32] = z1;
        __syncwarp();
        float o0, o1;
        mlp1p<64, true>((const float2*)(smf + OFF_W2), smf + OFF_B2, xb, lane, o0, o1);
        out[b * Dm + lane]      = o0;
        out[b * Dm + lane + 32] = o1;
        __syncwarp();
    }
}

// ---------------- launch ----------------------------------------------------
extern "C" void kernel_launch(void* const* d_in, const int* in_sizes, int n_in,
                              void* d_out, int out_size) {
    const int*   nodes_v = (const int*)d_in[0];
    const int*   neigh_u = (const int*)d_in[1];
    const int*   neigh_r = (const int*)d_in[2];
    const float* embed_u = (const float*)d_in[3];
    const float* embed_i = (const float*)d_in[4];
    const float* embed_r = (const float*)d_in[5];
    const float* gv_w1 = (const float*)d_in[6];
    const float* gv_b1 = (const float*)d_in[7];
    const float* gv_w2 = (const float*)d_in[8];
    const float* gv_b2 = (const float*)d_in[9];
    const float* gv_w3 = (const float*)d_in[10];
    const float* gv_b3 = (const float*)d_in[11];
    const float* at_w1 = (const float*)d_in[12];
    const float* at_b1 = (const float*)d_in[13];
    const float* at_w2 = (const float*)d_in[14];
    const float* at_b2 = (const float*)d_in[15];
    const float* at_w3 = (const float*)d_in[16];
    const float* at_b3 = (const float*)d_in[17];
    const float* wr1_w = (const float*)d_in[18];
    const float* wr1_b = (const float*)d_in[19];
    const float* wr2_w = (const float*)d_in[20];
    const float* wr2_b = (const float*)d_in[21];
    float* out = (float*)d_out;

    int nsm = 148;
    cudaDeviceGetAttribute(&nsm, cudaDevAttrMultiProcessorCount, 0);

    const size_t s1 = SMEM1_FLOATS * sizeof(float);
    const size_t s2 = SMEM2_FLOATS * sizeof(float);
    cudaFuncSetAttribute(k_rows, cudaFuncAttributeMaxDynamicSharedMemorySize, (int)s1);
    cudaFuncSetAttribute(k_agg,  cudaFuncAttributeMaxDynamicSharedMemorySize, (int)s2);

    k_rows<<<nsm, 32 * WARPS, s1>>>(nodes_v, neigh_u, neigh_r,
                                    embed_u, embed_i, embed_r,
                                    gv_w1, gv_b1, gv_w2, gv_b2, gv_w3, gv_b3,
                                    at_w1, at_b1, at_w2, at_b2, at_w3, at_b3);
    k_agg<<<AGG_GRID, 32 * AGG_WARPS, s2>>>(nodes_v, embed_i,
                                            wr1_w, wr1_b, wr2_w, wr2_b, out);
}